// round 13
// baseline (speedup 1.0000x reference)
#include <cuda_runtime.h>
#include <cuda_fp16.h>
#include <cstdint>
#include <cstddef>

// Problem constants
#define BATCH   16
#define CIN     256
#define HH      64
#define WW      64
#define HW      4096
#define OC_QKV  768
#define HEADS   64
#define ATT_CH  512
#define OC_OUT  256
#define K_PROJ  512

#define WSCALE    2048.0f
#define INV_WSCALE (1.0f / 2048.0f)

// ---------------------------------------------------------------------------
// fp16 hi/lo paired layout, 16-k chunks, 32 halves (64B) per row per chunk.
// slot s(p) = ((p&3)<<1)|(p>>2) for pair p=kk>>1; slot = 8B = [h_e,h_o,l_e,l_o].
// A 32-k GEMM chunk = two consecutive 16-k blocks = 128 contiguous bytes.
// ---------------------------------------------------------------------------
__device__ float  g_qkv [(size_t)BATCH * OC_QKV * HW];
__device__ float  g_agg [(size_t)BATCH * OC_QKV * HW];
__device__ float  g_kv  [(size_t)BATCH * HEADS * 4 * 72];
__device__ __half g_attp[(size_t)BATCH * HW * 2 * ATT_CH];  // paired fp16
__device__ __half g_xtp [(size_t)BATCH * HW * 2 * CIN];     // paired fp16
__device__ __half g_wqp [(size_t)OC_QKV * 2 * CIN];
__device__ __half g_wpp [(size_t)OC_OUT * 2 * K_PROJ];

// ---------------------------------------------------------------------------
// Helpers
// ---------------------------------------------------------------------------
__device__ __forceinline__ int slot_hi(int kk) {
    const int p = kk >> 1;
    const int s = ((p & 3) << 1) | (p >> 2);
    return s * 4 + (kk & 1);
}
__device__ __forceinline__ void mma_f16(float* d, const uint32_t* a, const uint32_t* b) {
    asm volatile(
        "mma.sync.aligned.m16n8k16.row.col.f32.f16.f16.f32 "
        "{%0,%1,%2,%3}, {%4,%5,%6,%7}, {%8,%9}, {%0,%1,%2,%3};"
        : "+f"(d[0]), "+f"(d[1]), "+f"(d[2]), "+f"(d[3])
        : "r"(a[0]), "r"(a[1]), "r"(a[2]), "r"(a[3]), "r"(b[0]), "r"(b[1]));
}
#define CP_ASYNC16(sa, gp) \
    asm volatile("cp.async.ca.shared.global [%0], [%1], 16;" :: "r"(sa), "l"(gp))
#define CP_COMMIT() asm volatile("cp.async.commit_group;")
#define CP_WAIT_ALL() asm volatile("cp.async.wait_group 0;")

// ---------------------------------------------------------------------------
// Splitter: fp32 [M,K] row-major -> fp16 hi/lo paired [m][K/16][32 halves]
// ---------------------------------------------------------------------------
__global__ __launch_bounds__(256)
void split_kernel(const float* __restrict__ in, __half* __restrict__ out,
                  int M, int K, float scale)
{
    const int i = blockIdx.x * 256 + threadIdx.x;
    if (i >= M * K) return;
    const int m = i / K;
    const int k = i - m * K;
    const float v = in[i] * scale;
    const __half h = __float2half_rn(v);
    const __half l = __float2half_rn(v - __half2float(h));
    __half* dst = out + ((size_t)m * (K >> 4) + (k >> 4)) * 32;
    const int off = slot_hi(k & 15);
    dst[off]     = h;
    dst[off + 2] = l;
}

// ---------------------------------------------------------------------------
// Unified fp16 3-term GEMM, K-chunk 32 (2 x k16 steps per sync):
//   C[z] = A * B[z]^T ; 3 MMAs per k16 step: AlBh, AhBl, AhBh (fp32 accum).
// Smem row = 144B (128B data + 16B pad): row stride ≡ 16 mod 128 ->
//   conflict-free fill STS and fragment LDS.128.
// Block 128x128, 2-stage cp.async, 2 CTAs/SM, 8 warps @ 32(M) x 64(N).
// ---------------------------------------------------------------------------
#define SROW 144
#define ATILE (128 * SROW)                 // 18432 B
#define STGB  (2 * ATILE)                  // 36864 B per stage (A + B)
#define GEMM_SMEM (2 * STGB)               // 73728 B

template<int NCH, bool BN>                 // NCH = K/32 chunks
__global__ __launch_bounds__(256, 2)
void gemm_fp16(const __half* __restrict__ Ap, const __half* __restrict__ Bp,
               float* __restrict__ C, int M,
               const float* __restrict__ gamma, const float* __restrict__ beta,
               const float* __restrict__ mean,  const float* __restrict__ var)
{
    extern __shared__ char sm[];
    const int tid  = threadIdx.x;
    const int wid  = tid >> 5;
    const int lane = tid & 31;
    const int g    = lane >> 2;
    const int tig  = lane & 3;

    const int n0 = blockIdx.x * 128;
    const int m0 = blockIdx.y * 128;
    const int z  = blockIdx.z;

    const int wm = (wid & 3) * 32;
    const int wn = (wid >> 2) * 64;

    constexpr int ROWB = NCH * 128;         // bytes per gmem row
    const char* Ab = (const char*)Ap;
    const char* Bb = (const char*)Bp + (size_t)z * HW * ROWB;
    float*      Cb = C + (size_t)z * M * HW;

    uint32_t smb;
    asm("{ .reg .u64 t; cvta.to.shared.u64 t, %1; cvt.u32.u64 %0, t; }" : "=r"(smb) : "l"(sm));

    // fill mapping: row = tid&127, uo = (tid>>7)*64 ; 4 x 16B per operand
    const int frow = tid & 127;
    const int uo   = (tid >> 7) * 64;
    const char* gA = Ab + (size_t)(m0 + frow) * ROWB + uo;
    const char* gB = Bb + (size_t)(n0 + frow) * ROWB + uo;
    const uint32_t sA0 = smb + (uint32_t)(frow * SROW + uo);
    const uint32_t sB0 = sA0 + (uint32_t)ATILE;

    float acc[2][8][4];
    #pragma unroll
    for (int mt = 0; mt < 2; mt++)
        #pragma unroll
        for (int nt = 0; nt < 8; nt++)
            #pragma unroll
            for (int j = 0; j < 4; j++) acc[mt][nt][j] = 0.f;

    // prologue: chunk 0 -> stage 0
    #pragma unroll
    for (int j = 0; j < 4; j++) {
        CP_ASYNC16(sA0 + j * 16, gA + j * 16);
        CP_ASYNC16(sB0 + j * 16, gB + j * 16);
    }
    CP_COMMIT();
    gA += 128;
    gB += 128;

    for (int c = 0; c < NCH; c++) {
        CP_WAIT_ALL();
        __syncthreads();
        if (c + 1 < NCH) {
            const uint32_t so = ((c + 1) & 1) ? (uint32_t)STGB : 0u;
            #pragma unroll
            for (int j = 0; j < 4; j++) {
                CP_ASYNC16(sA0 + so + j * 16, gA + j * 16);
                CP_ASYNC16(sB0 + so + j * 16, gB + j * 16);
            }
            CP_COMMIT();
            gA += 128;
            gB += 128;
        }
        const char* As_ = sm + (c & 1) * STGB;
        const char* Bs_ = As_ + ATILE;

        #pragma unroll
        for (int ks = 0; ks < 2; ks++) {
            const int col = ks * 64 + tig * 16;
            float4 r1 = *(const float4*)(As_ + (wm + g     ) * SROW + col);
            float4 r2 = *(const float4*)(As_ + (wm + 8  + g) * SROW + col);
            float4 r3 = *(const float4*)(As_ + (wm + 16 + g) * SROW + col);
            float4 r4 = *(const float4*)(As_ + (wm + 24 + g) * SROW + col);
            uint32_t ahi0[4] = { __float_as_uint(r1.x), __float_as_uint(r2.x),
                                 __float_as_uint(r1.z), __float_as_uint(r2.z) };
            uint32_t alo0[4] = { __float_as_uint(r1.y), __float_as_uint(r2.y),
                                 __float_as_uint(r1.w), __float_as_uint(r2.w) };
            uint32_t ahi1[4] = { __float_as_uint(r3.x), __float_as_uint(r4.x),
                                 __float_as_uint(r3.z), __float_as_uint(r4.z) };
            uint32_t alo1[4] = { __float_as_uint(r3.y), __float_as_uint(r4.y),
                                 __float_as_uint(r3.w), __float_as_uint(r4.w) };

            #pragma unroll
            for (int np = 0; np < 4; np++) {
                const int na = np * 2;
                const int nb = na + 1;
                float4 rb0 = *(const float4*)(Bs_ + (wn + na * 8 + g) * SROW + col);
                float4 rb1 = *(const float4*)(Bs_ + (wn + nb * 8 + g) * SROW + col);
                uint32_t b0h[2] = { __float_as_uint(rb0.x), __float_as_uint(rb0.z) };
                uint32_t b0l[2] = { __float_as_uint(rb0.y), __float_as_uint(rb0.w) };
                uint32_t b1h[2] = { __float_as_uint(rb1.x), __float_as_uint(rb1.z) };
                uint32_t b1l[2] = { __float_as_uint(rb1.y), __float_as_uint(rb1.w) };
                mma_f16(acc[0][na], alo0, b0h);
                mma_f16(acc[1][na], alo1, b0h);
                mma_f16(acc[0][nb], alo0, b1h);
                mma_f16(acc[1][nb], alo1, b1h);
                mma_f16(acc[0][na], ahi0, b0l);
                mma_f16(acc[1][na], ahi1, b0l);
                mma_f16(acc[0][nb], ahi0, b1l);
                mma_f16(acc[1][nb], ahi1, b1l);
                mma_f16(acc[0][na], ahi0, b0h);
                mma_f16(acc[1][na], ahi1, b0h);
                mma_f16(acc[0][nb], ahi0, b1h);
                mma_f16(acc[1][nb], ahi1, b1h);
            }
        }
    }

    // epilogue (undo WSCALE; optional fused BN)
    #pragma unroll
    for (int mt = 0; mt < 2; mt++) {
        const int mA = m0 + wm + mt * 16 + g;
        const int mB = mA + 8;
        float sAa = INV_WSCALE, hA = 0.f, sBb = INV_WSCALE, hB = 0.f;
        if (BN) {
            const float invA = gamma[mA] * rsqrtf(var[mA] + 1e-5f);
            const float invB = gamma[mB] * rsqrtf(var[mB] + 1e-5f);
            sAa = invA * INV_WSCALE;
            hA  = beta[mA] - mean[mA] * invA;
            sBb = invB * INV_WSCALE;
            hB  = beta[mB] - mean[mB] * invB;
        }
        float* rowA = Cb + (size_t)mA * HW + n0 + wn + 2 * tig;
        float* rowB = Cb + (size_t)mB * HW + n0 + wn + 2 * tig;
        #pragma unroll
        for (int nt = 0; nt < 8; nt++) {
            *(float2*)(rowA + nt * 8) =
                make_float2(acc[mt][nt][0] * sAa + hA, acc[mt][nt][1] * sAa + hA);
            *(float2*)(rowB + nt * 8) =
                make_float2(acc[mt][nt][2] * sBb + hB, acc[mt][nt][3] * sBb + hB);
        }
    }
}

// ---------------------------------------------------------------------------
// Transpose x: [b][k=256][n] -> paired fp16 xt [b][n][16 chunks][32 halves]
// ---------------------------------------------------------------------------
__global__ __launch_bounds__(256)
void transpose_kernel(const float* __restrict__ in, __half* __restrict__ outp)
{
    __shared__ float t[32][33];
    const int b  = blockIdx.z;
    const int n0 = blockIdx.x * 32;
    const int k0 = blockIdx.y * 32;
    const int tx = threadIdx.x & 31;
    const int ty = threadIdx.x >> 5;

    const float* ib = in + (size_t)b * CIN * HW;
    __half* ob = outp + (size_t)b * HW * (2 * CIN);

    #pragma unroll
    for (int i = 0; i < 4; i++) {
        const int k = k0 + ty + i * 8;
        t[ty + i * 8][tx] = ib[(size_t)k * HW + n0 + tx];
    }
    __syncthreads();
    #pragma unroll
    for (int i = 0; i < 4; i++) {
        const int n = n0 + ty + i * 8;
        const int k = k0 + tx;
        const float v = t[tx][ty + i * 8];
        const __half h = __float2half_rn(v);
        const __half l = __float2half_rn(v - __half2float(h));
        __half* dst = ob + (size_t)n * (2 * CIN) + (k >> 4) * 32;
        const int off = slot_hi(k & 15);
        dst[off]     = h;
        dst[off + 2] = l;
    }
}

// ---------------------------------------------------------------------------
// Fused depthwise 3x3 + grouped 1x1 (fp32)
// ---------------------------------------------------------------------------
__global__ __launch_bounds__(256)
void dwpw_kernel(const float* __restrict__ qkv,
                 const float* __restrict__ wdw,
                 const float* __restrict__ wpw,
                 float* __restrict__ agg)
{
    const int strip = blockIdx.x;
    const int gg    = blockIdx.y;
    const int b     = blockIdx.z;
    const int r0    = strip * 16;

    __shared__ float s_in[8][18][68];
    __shared__ float s_wdw[8][9];
    __shared__ float s_wpw[8][8];

    const int tid = threadIdx.x;
    const float* base = qkv + ((size_t)b * OC_QKV + gg * 8) * HW;

    for (int idx = tid; idx < 8 * 18 * 16; idx += 256) {
        const int seg = idx & 15;
        const int row = idx >> 4;
        const int rr  = row % 18;
        const int ch  = row / 18;
        const int y   = r0 + rr - 1;
        float4 v = make_float4(0.f, 0.f, 0.f, 0.f);
        if (y >= 0 && y < HH)
            v = *(const float4*)(base + (size_t)ch * HW + y * WW + seg * 4);
        float* d = &s_in[ch][rr][1 + seg * 4];
        d[0] = v.x; d[1] = v.y; d[2] = v.z; d[3] = v.w;
        if (seg == 0)  s_in[ch][rr][0]  = 0.f;
        if (seg == 15) s_in[ch][rr][65] = 0.f;
    }
    if (tid < 72)
        s_wdw[tid / 9][tid % 9] = wdw[(size_t)(gg * 8 + tid / 9) * 9 + tid % 9];
    if (tid >= 128 && tid < 192) {
        int t = tid - 128;
        s_wpw[t >> 3][t & 7] = wpw[(size_t)(gg * 8 + (t >> 3)) * 8 + (t & 7)];
    }
    __syncthreads();

    float* obase = agg + ((size_t)b * OC_QKV + gg * 8) * HW + r0 * WW;
    for (int p = tid; p < 16 * WW; p += 256) {
        const int py = p >> 6;
        const int px = p & 63;
        float dwv[8];
        #pragma unroll
        for (int ic = 0; ic < 8; ic++) {
            float s = 0.f;
            #pragma unroll
            for (int ky = 0; ky < 3; ky++)
                #pragma unroll
                for (int kx = 0; kx < 3; kx++)
                    s += s_in[ic][py + ky][px + kx] * s_wdw[ic][ky * 3 + kx];
            dwv[ic] = s;
        }
        #pragma unroll
        for (int oc = 0; oc < 8; oc++) {
            float s = 0.f;
            #pragma unroll
            for (int ic = 0; ic < 8; ic++) s += s_wpw[oc][ic] * dwv[ic];
            obase[(size_t)oc * HW + p] = s;
        }
    }
}

// ---------------------------------------------------------------------------
// kv partial reduction over 4 n-segments
// ---------------------------------------------------------------------------
__global__ __launch_bounds__(256)
void kv_kernel(const float* __restrict__ qkv, const float* __restrict__ agg,
               float* __restrict__ kvout)
{
    const int h   = blockIdx.x;
    const int b   = blockIdx.y;
    const int seg = blockIdx.z;
    const float* src = (h < 32) ? qkv : agg;
    const int ch0 = (h & 31) * 24;
    const float* base = src + ((size_t)b * OC_QKV + ch0) * HW;

    float acc[8][9];
    #pragma unroll
    for (int d = 0; d < 8; d++)
        #pragma unroll
        for (int e = 0; e < 9; e++) acc[d][e] = 0.f;

    const int nend = (seg + 1) * 1024;
    for (int n = seg * 1024 + threadIdx.x; n < nend; n += 256) {
        float kk[8], vv[8];
        #pragma unroll
        for (int d = 0; d < 8; d++)
            kk[d] = fmaxf(base[(size_t)(8 + d) * HW + n], 0.f);
        #pragma unroll
        for (int e = 0; e < 8; e++)
            vv[e] = base[(size_t)(16 + e) * HW + n];
        #pragma unroll
        for (int d = 0; d < 8; d++) {
            #pragma unroll
            for (int e = 0; e < 8; e++) acc[d][e] += kk[d] * vv[e];
            acc[d][8] += kk[d];
        }
    }

    __shared__ float sred[8][72];
    const int lane = threadIdx.x & 31;
    const int warp = threadIdx.x >> 5;
    #pragma unroll
    for (int d = 0; d < 8; d++)
        #pragma unroll
        for (int e = 0; e < 9; e++) {
            float v = acc[d][e];
            #pragma unroll
            for (int o = 16; o > 0; o >>= 1)
                v += __shfl_down_sync(0xffffffffu, v, o);
            if (lane == 0) sred[warp][d * 9 + e] = v;
        }
    __syncthreads();
    if (threadIdx.x < 72) {
        float s = 0.f;
        #pragma unroll
        for (int w = 0; w < 8; w++) s += sred[w][threadIdx.x];
        kvout[(((size_t)b * HEADS + h) * 4 + seg) * 72 + threadIdx.x] = s;
    }
}

// ---------------------------------------------------------------------------
// attention apply -> paired fp16 att. Head h: chunk h>>1, slots (j<<1)|(h&1).
// ---------------------------------------------------------------------------
__global__ __launch_bounds__(256)
void apply_kernel(const float* __restrict__ qkv, const float* __restrict__ agg,
                  const float* __restrict__ kvin, __half* __restrict__ attp)
{
    const int h = blockIdx.x;
    const int b = blockIdx.y;
    const float* src = (h < 32) ? qkv : agg;
    const int ch0 = (h & 31) * 24;
    const float* qb = src + ((size_t)b * OC_QKV + ch0) * HW;

    __shared__ float s_kv[72];
    if (threadIdx.x < 72) {
        const float* kp = kvin + ((size_t)b * HEADS + h) * 4 * 72 + threadIdx.x;
        s_kv[threadIdx.x] = kp[0] + kp[72] + kp[144] + kp[216];
    }
    __syncthreads();

    char* ob = (char*)attp + (size_t)b * HW * 2048 + (h >> 1) * 64;
    const int hodd = h & 1;
    for (int n = threadIdx.x; n < HW; n += 256) {
        float q[8];
        #pragma unroll
        for (int d = 0; d < 8; d++)
            q[d] = fmaxf(qb[(size_t)d * HW + n], 0.f);
        float num[9];
        #pragma unroll
        for (int e = 0; e < 9; e++) {
            float s = 0.f;
            #pragma unroll
            for (int d = 0; d < 8; d++) s += q[d] * s_kv[d * 9 + e];
            num[e] = s;
        }
        const float r = 1.0f / (num[8] + 1e-15f);
        char* p = ob + (size_t)n * 2048;
        #pragma unroll
        for (int j = 0; j < 4; j++) {
            const float v0 = num[2 * j] * r;
            const float v1 = num[2 * j + 1] * r;
            const __half h0 = __float2half_rn(v0);
            const __half h1 = __float2half_rn(v1);
            const __half l0 = __float2half_rn(v0 - __half2float(h0));
            const __half l1 = __float2half_rn(v1 - __half2float(h1));
            __half2 ph = __halves2half2(h0, h1);
            __half2 pl = __halves2half2(l0, l1);
            uint2 w;
            w.x = *reinterpret_cast<unsigned*>(&ph);
            w.y = *reinterpret_cast<unsigned*>(&pl);
            *(uint2*)(p + ((j << 1) | hodd) * 8) = w;
        }
    }
}

// ---------------------------------------------------------------------------
// Launch
// ---------------------------------------------------------------------------
extern "C" void kernel_launch(void* const* d_in, const int* in_sizes, int n_in,
                              void* d_out, int out_size)
{
    const float* x      = (const float*)d_in[0];
    const float* w_qkv  = (const float*)d_in[1];
    const float* w_dw   = (const float*)d_in[2];
    const float* w_pw   = (const float*)d_in[3];
    const float* w_proj = (const float*)d_in[4];
    const float* gamma  = (const float*)d_in[5];
    const float* beta   = (const float*)d_in[6];
    const float* mean   = (const float*)d_in[7];
    const float* var    = (const float*)d_in[8];
    float* out = (float*)d_out;

    float *qkv_p, *agg_p, *kv_p;
    __half *attp_p, *xtp_p, *wqp_p, *wpp_p;
    cudaGetSymbolAddress((void**)&qkv_p,  g_qkv);
    cudaGetSymbolAddress((void**)&agg_p,  g_agg);
    cudaGetSymbolAddress((void**)&kv_p,   g_kv);
    cudaGetSymbolAddress((void**)&attp_p, g_attp);
    cudaGetSymbolAddress((void**)&xtp_p,  g_xtp);
    cudaGetSymbolAddress((void**)&wqp_p,  g_wqp);
    cudaGetSymbolAddress((void**)&wpp_p,  g_wpp);

    cudaFuncSetAttribute(gemm_fp16<8, false>,
                         cudaFuncAttributeMaxDynamicSharedMemorySize, GEMM_SMEM);
    cudaFuncSetAttribute(gemm_fp16<16, true>,
                         cudaFuncAttributeMaxDynamicSharedMemorySize, GEMM_SMEM);

    split_kernel<<<(OC_QKV * CIN + 255) / 256, 256>>>(w_qkv, wqp_p, OC_QKV, CIN, WSCALE);
    split_kernel<<<(OC_OUT * K_PROJ + 255) / 256, 256>>>(w_proj, wpp_p, OC_OUT, K_PROJ, WSCALE);
    {
        dim3 grid(HW / 32, CIN / 32, BATCH);
        transpose_kernel<<<grid, 256>>>(x, xtp_p);
    }
    // 1) qkv = W_qkv * x : fp16 3-term, K=256 -> NCH=8
    {
        dim3 grid(HW / 128, OC_QKV / 128, BATCH);
        gemm_fp16<8, false><<<grid, 256, GEMM_SMEM>>>(wqp_p, xtp_p, qkv_p, OC_QKV,
                                                      nullptr, nullptr, nullptr, nullptr);
    }
    // 2) depthwise + grouped pointwise
    {
        dim3 grid(4, 96, BATCH);
        dwpw_kernel<<<grid, 256>>>(qkv_p, w_dw, w_pw, agg_p);
    }
    // 3) kv partial reduction
    {
        dim3 grid(HEADS, BATCH, 4);
        kv_kernel<<<grid, 256>>>(qkv_p, agg_p, kv_p);
    }
    // 4) attention apply (paired fp16 att)
    {
        dim3 grid(HEADS, BATCH);
        apply_kernel<<<grid, 256>>>(qkv_p, agg_p, kv_p, attp_p);
    }
    // 5) y = W_proj * att + BN : fp16 3-term, K=512 -> NCH=16
    {
        dim3 grid(HW / 128, OC_OUT / 128, BATCH);
        gemm_fp16<16, true><<<grid, 256, GEMM_SMEM>>>(wpp_p, attp_p, out, OC_OUT,
                                                      gamma, beta, mean, var);
    }
}

// round 14
// speedup vs baseline: 1.2557x; 1.2557x over previous
#include <cuda_runtime.h>
#include <cuda_fp16.h>
#include <cstdint>
#include <cstddef>

// Problem constants
#define BATCH   16
#define CIN     256
#define HH      64
#define WW      64
#define HW      4096
#define OC_QKV  768
#define HEADS   64
#define ATT_CH  512
#define OC_OUT  256
#define K_PROJ  512

#define WSCALE    2048.0f
#define INV_WSCALE (1.0f / 2048.0f)

// ---------------------------------------------------------------------------
// fp16 hi/lo paired layout, 16-k chunks, 32 halves (64B) per row per chunk.
// slot s(p) = ((p&3)<<1)|(p>>2) for pair p=kk>>1; slot = 8B = [h_e,h_o,l_e,l_o].
// A 32-k GEMM chunk = two consecutive 16-k blocks = 128 contiguous bytes.
// ---------------------------------------------------------------------------
__device__ float  g_qkv [(size_t)BATCH * OC_QKV * HW];
__device__ float  g_agg [(size_t)BATCH * OC_QKV * HW];
__device__ float  g_kv  [(size_t)BATCH * HEADS * 4 * 72];
__device__ __half g_attp[(size_t)BATCH * HW * 2 * ATT_CH];  // paired fp16
__device__ __half g_xtp [(size_t)BATCH * HW * 2 * CIN];     // paired fp16
__device__ __half g_wqp [(size_t)OC_QKV * 2 * CIN];
__device__ __half g_wpp [(size_t)OC_OUT * 2 * K_PROJ];

// ---------------------------------------------------------------------------
// Helpers
// ---------------------------------------------------------------------------
__device__ __forceinline__ int slot_hi(int kk) {
    const int p = kk >> 1;
    const int s = ((p & 3) << 1) | (p >> 2);
    return s * 4 + (kk & 1);
}
__device__ __forceinline__ void mma_f16(float* d, const uint32_t* a, const uint32_t* b) {
    asm volatile(
        "mma.sync.aligned.m16n8k16.row.col.f32.f16.f16.f32 "
        "{%0,%1,%2,%3}, {%4,%5,%6,%7}, {%8,%9}, {%0,%1,%2,%3};"
        : "+f"(d[0]), "+f"(d[1]), "+f"(d[2]), "+f"(d[3])
        : "r"(a[0]), "r"(a[1]), "r"(a[2]), "r"(a[3]), "r"(b[0]), "r"(b[1]));
}
#define CP_ASYNC16(sa, gp) \
    asm volatile("cp.async.ca.shared.global [%0], [%1], 16;" :: "r"(sa), "l"(gp))
#define CP_COMMIT() asm volatile("cp.async.commit_group;")
#define CP_WAIT_ALL() asm volatile("cp.async.wait_group 0;")

// ---------------------------------------------------------------------------
// Splitter: fp32 [M,K] row-major -> fp16 hi/lo paired [m][K/16][32 halves]
// ---------------------------------------------------------------------------
__global__ __launch_bounds__(256)
void split_kernel(const float* __restrict__ in, __half* __restrict__ out,
                  int M, int K, float scale)
{
    const int i = blockIdx.x * 256 + threadIdx.x;
    if (i >= M * K) return;
    const int m = i / K;
    const int k = i - m * K;
    const float v = in[i] * scale;
    const __half h = __float2half_rn(v);
    const __half l = __float2half_rn(v - __half2float(h));
    __half* dst = out + ((size_t)m * (K >> 4) + (k >> 4)) * 32;
    const int off = slot_hi(k & 15);
    dst[off]     = h;
    dst[off + 2] = l;
}

// ---------------------------------------------------------------------------
// Unified fp16 3-term GEMM, K-chunk 32 (2 x k16 steps per sync):
//   C[z] = A * B[z]^T ; 3 MMAs per k16 step: AlBh, AhBl, AhBh (fp32 accum).
// SROW = 192 B (128B data + 64B pad): SROW mod 128 = 64 -> fragment LDS.128
// conflict-free (two g-rows per phase in disjoint 64B halves).
// Fill: row = tid>>3 (+32/it), 16B block j = tid&7 -> phase writes 8
// consecutive blocks of one row: STS conflict-free, gmem 128B coalesced.
// Block 128x128, 2-stage cp.async, 2 CTAs/SM, 8 warps @ 32(M) x 64(N).
// ---------------------------------------------------------------------------
#define SROW 192
#define ATILE (128 * SROW)                 // 24576 B
#define STGB  (2 * ATILE)                  // 49152 B per stage (A + B)
#define GEMM_SMEM (2 * STGB)               // 98304 B

template<int NCH, bool BN>                 // NCH = K/32 chunks
__global__ __launch_bounds__(256, 2)
void gemm_fp16(const __half* __restrict__ Ap, const __half* __restrict__ Bp,
               float* __restrict__ C, int M,
               const float* __restrict__ gamma, const float* __restrict__ beta,
               const float* __restrict__ mean,  const float* __restrict__ var)
{
    extern __shared__ char sm[];
    const int tid  = threadIdx.x;
    const int wid  = tid >> 5;
    const int lane = tid & 31;
    const int g    = lane >> 2;
    const int tig  = lane & 3;

    const int n0 = blockIdx.x * 128;
    const int m0 = blockIdx.y * 128;
    const int z  = blockIdx.z;

    const int wm = (wid & 3) * 32;
    const int wn = (wid >> 2) * 64;

    constexpr int ROWB = NCH * 128;         // bytes per gmem row
    const char* Ab = (const char*)Ap;
    const char* Bb = (const char*)Bp + (size_t)z * HW * ROWB;
    float*      Cb = C + (size_t)z * M * HW;

    uint32_t smb;
    asm("{ .reg .u64 t; cvta.to.shared.u64 t, %1; cvt.u32.u64 %0, t; }" : "=r"(smb) : "l"(sm));

    // fill mapping: row = tid>>3 (+32 per it, 4 its), 16B block j = tid&7
    const int frow = tid >> 3;              // 0..31
    const int j16  = (tid & 7) * 16;
    const char* gA = Ab + (size_t)(m0 + frow) * ROWB + j16;
    const char* gB = Bb + (size_t)(n0 + frow) * ROWB + j16;
    const uint32_t sA0 = smb + (uint32_t)(frow * SROW + j16);
    const uint32_t sB0 = sA0 + (uint32_t)ATILE;

    float acc[2][8][4];
    #pragma unroll
    for (int mt = 0; mt < 2; mt++)
        #pragma unroll
        for (int nt = 0; nt < 8; nt++)
            #pragma unroll
            for (int j = 0; j < 4; j++) acc[mt][nt][j] = 0.f;

    // prologue: chunk 0 -> stage 0
    #pragma unroll
    for (int it = 0; it < 4; it++) {
        CP_ASYNC16(sA0 + (uint32_t)(it * 32 * SROW), gA + (size_t)it * 32 * ROWB);
        CP_ASYNC16(sB0 + (uint32_t)(it * 32 * SROW), gB + (size_t)it * 32 * ROWB);
    }
    CP_COMMIT();
    gA += 128;
    gB += 128;

    for (int c = 0; c < NCH; c++) {
        CP_WAIT_ALL();
        __syncthreads();
        if (c + 1 < NCH) {
            const uint32_t so = ((c + 1) & 1) ? (uint32_t)STGB : 0u;
            #pragma unroll
            for (int it = 0; it < 4; it++) {
                CP_ASYNC16(sA0 + so + (uint32_t)(it * 32 * SROW),
                           gA + (size_t)it * 32 * ROWB);
                CP_ASYNC16(sB0 + so + (uint32_t)(it * 32 * SROW),
                           gB + (size_t)it * 32 * ROWB);
            }
            CP_COMMIT();
            gA += 128;
            gB += 128;
        }
        const char* As_ = sm + (c & 1) * STGB;
        const char* Bs_ = As_ + ATILE;

        #pragma unroll
        for (int ks = 0; ks < 2; ks++) {
            const int col = ks * 64 + tig * 16;
            float4 r1 = *(const float4*)(As_ + (wm + g     ) * SROW + col);
            float4 r2 = *(const float4*)(As_ + (wm + 8  + g) * SROW + col);
            float4 r3 = *(const float4*)(As_ + (wm + 16 + g) * SROW + col);
            float4 r4 = *(const float4*)(As_ + (wm + 24 + g) * SROW + col);
            uint32_t ahi0[4] = { __float_as_uint(r1.x), __float_as_uint(r2.x),
                                 __float_as_uint(r1.z), __float_as_uint(r2.z) };
            uint32_t alo0[4] = { __float_as_uint(r1.y), __float_as_uint(r2.y),
                                 __float_as_uint(r1.w), __float_as_uint(r2.w) };
            uint32_t ahi1[4] = { __float_as_uint(r3.x), __float_as_uint(r4.x),
                                 __float_as_uint(r3.z), __float_as_uint(r4.z) };
            uint32_t alo1[4] = { __float_as_uint(r3.y), __float_as_uint(r4.y),
                                 __float_as_uint(r3.w), __float_as_uint(r4.w) };

            #pragma unroll
            for (int np = 0; np < 4; np++) {
                const int na = np * 2;
                const int nb = na + 1;
                float4 rb0 = *(const float4*)(Bs_ + (wn + na * 8 + g) * SROW + col);
                float4 rb1 = *(const float4*)(Bs_ + (wn + nb * 8 + g) * SROW + col);
                uint32_t b0h[2] = { __float_as_uint(rb0.x), __float_as_uint(rb0.z) };
                uint32_t b0l[2] = { __float_as_uint(rb0.y), __float_as_uint(rb0.w) };
                uint32_t b1h[2] = { __float_as_uint(rb1.x), __float_as_uint(rb1.z) };
                uint32_t b1l[2] = { __float_as_uint(rb1.y), __float_as_uint(rb1.w) };
                mma_f16(acc[0][na], alo0, b0h);
                mma_f16(acc[1][na], alo1, b0h);
                mma_f16(acc[0][nb], alo0, b1h);
                mma_f16(acc[1][nb], alo1, b1h);
                mma_f16(acc[0][na], ahi0, b0l);
                mma_f16(acc[1][na], ahi1, b0l);
                mma_f16(acc[0][nb], ahi0, b1l);
                mma_f16(acc[1][nb], ahi1, b1l);
                mma_f16(acc[0][na], ahi0, b0h);
                mma_f16(acc[1][na], ahi1, b0h);
                mma_f16(acc[0][nb], ahi0, b1h);
                mma_f16(acc[1][nb], ahi1, b1h);
            }
        }
    }

    // epilogue (undo WSCALE; optional fused BN)
    #pragma unroll
    for (int mt = 0; mt < 2; mt++) {
        const int mA = m0 + wm + mt * 16 + g;
        const int mB = mA + 8;
        float sAa = INV_WSCALE, hA = 0.f, sBb = INV_WSCALE, hB = 0.f;
        if (BN) {
            const float invA = gamma[mA] * rsqrtf(var[mA] + 1e-5f);
            const float invB = gamma[mB] * rsqrtf(var[mB] + 1e-5f);
            sAa = invA * INV_WSCALE;
            hA  = beta[mA] - mean[mA] * invA;
            sBb = invB * INV_WSCALE;
            hB  = beta[mB] - mean[mB] * invB;
        }
        float* rowA = Cb + (size_t)mA * HW + n0 + wn + 2 * tig;
        float* rowB = Cb + (size_t)mB * HW + n0 + wn + 2 * tig;
        #pragma unroll
        for (int nt = 0; nt < 8; nt++) {
            *(float2*)(rowA + nt * 8) =
                make_float2(acc[mt][nt][0] * sAa + hA, acc[mt][nt][1] * sAa + hA);
            *(float2*)(rowB + nt * 8) =
                make_float2(acc[mt][nt][2] * sBb + hB, acc[mt][nt][3] * sBb + hB);
        }
    }
}

// ---------------------------------------------------------------------------
// Transpose x: [b][k=256][n] -> paired fp16 xt [b][n][16 chunks][32 halves]
// ---------------------------------------------------------------------------
__global__ __launch_bounds__(256)
void transpose_kernel(const float* __restrict__ in, __half* __restrict__ outp)
{
    __shared__ float t[32][33];
    const int b  = blockIdx.z;
    const int n0 = blockIdx.x * 32;
    const int k0 = blockIdx.y * 32;
    const int tx = threadIdx.x & 31;
    const int ty = threadIdx.x >> 5;

    const float* ib = in + (size_t)b * CIN * HW;
    __half* ob = outp + (size_t)b * HW * (2 * CIN);

    #pragma unroll
    for (int i = 0; i < 4; i++) {
        const int k = k0 + ty + i * 8;
        t[ty + i * 8][tx] = ib[(size_t)k * HW + n0 + tx];
    }
    __syncthreads();
    #pragma unroll
    for (int i = 0; i < 4; i++) {
        const int n = n0 + ty + i * 8;
        const int k = k0 + tx;
        const float v = t[tx][ty + i * 8];
        const __half h = __float2half_rn(v);
        const __half l = __float2half_rn(v - __half2float(h));
        __half* dst = ob + (size_t)n * (2 * CIN) + (k >> 4) * 32;
        const int off = slot_hi(k & 15);
        dst[off]     = h;
        dst[off + 2] = l;
    }
}

// ---------------------------------------------------------------------------
// Fused depthwise 3x3 + grouped 1x1 (fp32)
// ---------------------------------------------------------------------------
__global__ __launch_bounds__(256)
void dwpw_kernel(const float* __restrict__ qkv,
                 const float* __restrict__ wdw,
                 const float* __restrict__ wpw,
                 float* __restrict__ agg)
{
    const int strip = blockIdx.x;
    const int gg    = blockIdx.y;
    const int b     = blockIdx.z;
    const int r0    = strip * 16;

    __shared__ float s_in[8][18][68];
    __shared__ float s_wdw[8][9];
    __shared__ float s_wpw[8][8];

    const int tid = threadIdx.x;
    const float* base = qkv + ((size_t)b * OC_QKV + gg * 8) * HW;

    for (int idx = tid; idx < 8 * 18 * 16; idx += 256) {
        const int seg = idx & 15;
        const int row = idx >> 4;
        const int rr  = row % 18;
        const int ch  = row / 18;
        const int y   = r0 + rr - 1;
        float4 v = make_float4(0.f, 0.f, 0.f, 0.f);
        if (y >= 0 && y < HH)
            v = *(const float4*)(base + (size_t)ch * HW + y * WW + seg * 4);
        float* d = &s_in[ch][rr][1 + seg * 4];
        d[0] = v.x; d[1] = v.y; d[2] = v.z; d[3] = v.w;
        if (seg == 0)  s_in[ch][rr][0]  = 0.f;
        if (seg == 15) s_in[ch][rr][65] = 0.f;
    }
    if (tid < 72)
        s_wdw[tid / 9][tid % 9] = wdw[(size_t)(gg * 8 + tid / 9) * 9 + tid % 9];
    if (tid >= 128 && tid < 192) {
        int t = tid - 128;
        s_wpw[t >> 3][t & 7] = wpw[(size_t)(gg * 8 + (t >> 3)) * 8 + (t & 7)];
    }
    __syncthreads();

    float* obase = agg + ((size_t)b * OC_QKV + gg * 8) * HW + r0 * WW;
    for (int p = tid; p < 16 * WW; p += 256) {
        const int py = p >> 6;
        const int px = p & 63;
        float dwv[8];
        #pragma unroll
        for (int ic = 0; ic < 8; ic++) {
            float s = 0.f;
            #pragma unroll
            for (int ky = 0; ky < 3; ky++)
                #pragma unroll
                for (int kx = 0; kx < 3; kx++)
                    s += s_in[ic][py + ky][px + kx] * s_wdw[ic][ky * 3 + kx];
            dwv[ic] = s;
        }
        #pragma unroll
        for (int oc = 0; oc < 8; oc++) {
            float s = 0.f;
            #pragma unroll
            for (int ic = 0; ic < 8; ic++) s += s_wpw[oc][ic] * dwv[ic];
            obase[(size_t)oc * HW + p] = s;
        }
    }
}

// ---------------------------------------------------------------------------
// kv partial reduction over 4 n-segments
// ---------------------------------------------------------------------------
__global__ __launch_bounds__(256)
void kv_kernel(const float* __restrict__ qkv, const float* __restrict__ agg,
               float* __restrict__ kvout)
{
    const int h   = blockIdx.x;
    const int b   = blockIdx.y;
    const int seg = blockIdx.z;
    const float* src = (h < 32) ? qkv : agg;
    const int ch0 = (h & 31) * 24;
    const float* base = src + ((size_t)b * OC_QKV + ch0) * HW;

    float acc[8][9];
    #pragma unroll
    for (int d = 0; d < 8; d++)
        #pragma unroll
        for (int e = 0; e < 9; e++) acc[d][e] = 0.f;

    const int nend = (seg + 1) * 1024;
    for (int n = seg * 1024 + threadIdx.x; n < nend; n += 256) {
        float kk[8], vv[8];
        #pragma unroll
        for (int d = 0; d < 8; d++)
            kk[d] = fmaxf(base[(size_t)(8 + d) * HW + n], 0.f);
        #pragma unroll
        for (int e = 0; e < 8; e++)
            vv[e] = base[(size_t)(16 + e) * HW + n];
        #pragma unroll
        for (int d = 0; d < 8; d++) {
            #pragma unroll
            for (int e = 0; e < 8; e++) acc[d][e] += kk[d] * vv[e];
            acc[d][8] += kk[d];
        }
    }

    __shared__ float sred[8][72];
    const int lane = threadIdx.x & 31;
    const int warp = threadIdx.x >> 5;
    #pragma unroll
    for (int d = 0; d < 8; d++)
        #pragma unroll
        for (int e = 0; e < 9; e++) {
            float v = acc[d][e];
            #pragma unroll
            for (int o = 16; o > 0; o >>= 1)
                v += __shfl_down_sync(0xffffffffu, v, o);
            if (lane == 0) sred[warp][d * 9 + e] = v;
        }
    __syncthreads();
    if (threadIdx.x < 72) {
        float s = 0.f;
        #pragma unroll
        for (int w = 0; w < 8; w++) s += sred[w][threadIdx.x];
        kvout[(((size_t)b * HEADS + h) * 4 + seg) * 72 + threadIdx.x] = s;
    }
}

// ---------------------------------------------------------------------------
// attention apply -> paired fp16 att. Head h: chunk h>>1, slots (j<<1)|(h&1).
// ---------------------------------------------------------------------------
__global__ __launch_bounds__(256)
void apply_kernel(const float* __restrict__ qkv, const float* __restrict__ agg,
                  const float* __restrict__ kvin, __half* __restrict__ attp)
{
    const int h = blockIdx.x;
    const int b = blockIdx.y;
    const float* src = (h < 32) ? qkv : agg;
    const int ch0 = (h & 31) * 24;
    const float* qb = src + ((size_t)b * OC_QKV + ch0) * HW;

    __shared__ float s_kv[72];
    if (threadIdx.x < 72) {
        const float* kp = kvin + ((size_t)b * HEADS + h) * 4 * 72 + threadIdx.x;
        s_kv[threadIdx.x] = kp[0] + kp[72] + kp[144] + kp[216];
    }
    __syncthreads();

    char* ob = (char*)attp + (size_t)b * HW * 2048 + (h >> 1) * 64;
    const int hodd = h & 1;
    for (int n = threadIdx.x; n < HW; n += 256) {
        float q[8];
        #pragma unroll
        for (int d = 0; d < 8; d++)
            q[d] = fmaxf(qb[(size_t)d * HW + n], 0.f);
        float num[9];
        #pragma unroll
        for (int e = 0; e < 9; e++) {
            float s = 0.f;
            #pragma unroll
            for (int d = 0; d < 8; d++) s += q[d] * s_kv[d * 9 + e];
            num[e] = s;
        }
        const float r = 1.0f / (num[8] + 1e-15f);
        char* p = ob + (size_t)n * 2048;
        #pragma unroll
        for (int j = 0; j < 4; j++) {
            const float v0 = num[2 * j] * r;
            const float v1 = num[2 * j + 1] * r;
            const __half h0 = __float2half_rn(v0);
            const __half h1 = __float2half_rn(v1);
            const __half l0 = __float2half_rn(v0 - __half2float(h0));
            const __half l1 = __float2half_rn(v1 - __half2float(h1));
            __half2 ph = __halves2half2(h0, h1);
            __half2 pl = __halves2half2(l0, l1);
            uint2 w;
            w.x = *reinterpret_cast<unsigned*>(&ph);
            w.y = *reinterpret_cast<unsigned*>(&pl);
            *(uint2*)(p + ((j << 1) | hodd) * 8) = w;
        }
    }
}

// ---------------------------------------------------------------------------
// Launch
// ---------------------------------------------------------------------------
extern "C" void kernel_launch(void* const* d_in, const int* in_sizes, int n_in,
                              void* d_out, int out_size)
{
    const float* x      = (const float*)d_in[0];
    const float* w_qkv  = (const float*)d_in[1];
    const float* w_dw   = (const float*)d_in[2];
    const float* w_pw   = (const float*)d_in[3];
    const float* w_proj = (const float*)d_in[4];
    const float* gamma  = (const float*)d_in[5];
    const float* beta   = (const float*)d_in[6];
    const float* mean   = (const float*)d_in[7];
    const float* var    = (const float*)d_in[8];
    float* out = (float*)d_out;

    float *qkv_p, *agg_p, *kv_p;
    __half *attp_p, *xtp_p, *wqp_p, *wpp_p;
    cudaGetSymbolAddress((void**)&qkv_p,  g_qkv);
    cudaGetSymbolAddress((void**)&agg_p,  g_agg);
    cudaGetSymbolAddress((void**)&kv_p,   g_kv);
    cudaGetSymbolAddress((void**)&attp_p, g_attp);
    cudaGetSymbolAddress((void**)&xtp_p,  g_xtp);
    cudaGetSymbolAddress((void**)&wqp_p,  g_wqp);
    cudaGetSymbolAddress((void**)&wpp_p,  g_wpp);

    cudaFuncSetAttribute(gemm_fp16<8, false>,
                         cudaFuncAttributeMaxDynamicSharedMemorySize, GEMM_SMEM);
    cudaFuncSetAttribute(gemm_fp16<16, true>,
                         cudaFuncAttributeMaxDynamicSharedMemorySize, GEMM_SMEM);

    split_kernel<<<(OC_QKV * CIN + 255) / 256, 256>>>(w_qkv, wqp_p, OC_QKV, CIN, WSCALE);
    split_kernel<<<(OC_OUT * K_PROJ + 255) / 256, 256>>>(w_proj, wpp_p, OC_OUT, K_PROJ, WSCALE);
    {
        dim3 grid(HW / 32, CIN / 32, BATCH);
        transpose_kernel<<<grid, 256>>>(x, xtp_p);
    }
    // 1) qkv = W_qkv * x : fp16 3-term, K=256 -> NCH=8
    {
        dim3 grid(HW / 128, OC_QKV / 128, BATCH);
        gemm_fp16<8, false><<<grid, 256, GEMM_SMEM>>>(wqp_p, xtp_p, qkv_p, OC_QKV,
                                                      nullptr, nullptr, nullptr, nullptr);
    }
    // 2) depthwise + grouped pointwise
    {
        dim3 grid(4, 96, BATCH);
        dwpw_kernel<<<grid, 256>>>(qkv_p, w_dw, w_pw, agg_p);
    }
    // 3) kv partial reduction
    {
        dim3 grid(HEADS, BATCH, 4);
        kv_kernel<<<grid, 256>>>(qkv_p, agg_p, kv_p);
    }
    // 4) attention apply (paired fp16 att)
    {
        dim3 grid(HEADS, BATCH);
        apply_kernel<<<grid, 256>>>(qkv_p, agg_p, kv_p, attp_p);
    }
    // 5) y = W_proj * att + BN : fp16 3-term, K=512 -> NCH=16
    {
        dim3 grid(HW / 128, OC_OUT / 128, BATCH);
        gemm_fp16<16, true><<<grid, 256, GEMM_SMEM>>>(wpp_p, attp_p, out, OC_OUT,
                                                      gamma, beta, mean, var);
    }
}

// round 16
// speedup vs baseline: 1.3662x; 1.0880x over previous
#include <cuda_runtime.h>
#include <cuda_fp16.h>
#include <cstdint>
#include <cstddef>

// Problem constants
#define BATCH   16
#define CIN     256
#define HH      64
#define WW      64
#define HW      4096
#define OC_QKV  768
#define HEADS   64
#define ATT_CH  512
#define OC_OUT  256
#define K_PROJ  512

#define WSCALE    2048.0f
#define INV_WSCALE (1.0f / 2048.0f)

// ---------------------------------------------------------------------------
// fp16 hi/lo paired layout, 16-k chunks, 32 halves (64B) per row per chunk.
// slot s(p) = ((p&3)<<1)|(p>>2) for pair p=kk>>1; slot = 8B = [h_e,h_o,l_e,l_o].
// ---------------------------------------------------------------------------
__device__ float  g_qkv [(size_t)BATCH * OC_QKV * HW];
__device__ float  g_agg [(size_t)BATCH * OC_QKV * HW];
__device__ float  g_kv  [(size_t)BATCH * HEADS * 4 * 72];
__device__ __half g_attp[(size_t)BATCH * HW * 2 * ATT_CH];  // paired fp16 (lo=0)
__device__ __half g_xtp [(size_t)BATCH * HW * 2 * CIN];     // paired fp16
__device__ __half g_wqp [(size_t)OC_QKV * 2 * CIN];
__device__ __half g_wpp [(size_t)OC_OUT * 2 * K_PROJ];

// ---------------------------------------------------------------------------
// Helpers
// ---------------------------------------------------------------------------
__device__ __forceinline__ int slot_hi(int kk) {
    const int p = kk >> 1;
    const int s = ((p & 3) << 1) | (p >> 2);
    return s * 4 + (kk & 1);
}
__device__ __forceinline__ void mma_f16(float* d, const uint32_t* a, const uint32_t* b) {
    asm volatile(
        "mma.sync.aligned.m16n8k16.row.col.f32.f16.f16.f32 "
        "{%0,%1,%2,%3}, {%4,%5,%6,%7}, {%8,%9}, {%0,%1,%2,%3};"
        : "+f"(d[0]), "+f"(d[1]), "+f"(d[2]), "+f"(d[3])
        : "r"(a[0]), "r"(a[1]), "r"(a[2]), "r"(a[3]), "r"(b[0]), "r"(b[1]));
}
#define CP_ASYNC16(sa, gp) \
    asm volatile("cp.async.ca.shared.global [%0], [%1], 16;" :: "r"(sa), "l"(gp))
#define CP_COMMIT() asm volatile("cp.async.commit_group;")
#define CP_WAIT_ALL() asm volatile("cp.async.wait_group 0;")

// ---------------------------------------------------------------------------
// Splitter: fp32 [M,K] row-major -> fp16 hi/lo paired [m][K/16][32 halves]
// ---------------------------------------------------------------------------
__global__ __launch_bounds__(256)
void split_kernel(const float* __restrict__ in, __half* __restrict__ out,
                  int M, int K, float scale)
{
    const int i = blockIdx.x * 256 + threadIdx.x;
    if (i >= M * K) return;
    const int m = i / K;
    const int k = i - m * K;
    const float v = in[i] * scale;
    const __half h = __float2half_rn(v);
    const __half l = __float2half_rn(v - __half2float(h));
    __half* dst = out + ((size_t)m * (K >> 4) + (k >> 4)) * 32;
    const int off = slot_hi(k & 15);
    dst[off]     = h;
    dst[off + 2] = l;
}

// ---------------------------------------------------------------------------
// Unified fp16 GEMM, K-chunk 32 (2 x k16 per sync), TERMS = 3 or 2:
//   3: AlBh + AhBl + AhBh  (fp32-grade)
//   2: AlBh + AhBh         (A exact, B single-rounded — terminal GEMM only)
// SROW = 192 (128B data + 64B pad, ≡64 mod 128): conflict-free frags + fill.
// Block 128x128, 2-stage cp.async, 2 CTAs/SM, 8 warps @ 32(M) x 64(N).
// ---------------------------------------------------------------------------
#define SROW 192
#define ATILE (128 * SROW)
#define STGB  (2 * ATILE)
#define GEMM_SMEM (2 * STGB)               // 98304 B

template<int NCH, int TERMS, bool BN>      // NCH = K/32 chunks
__global__ __launch_bounds__(256, 2)
void gemm_fp16(const __half* __restrict__ Ap, const __half* __restrict__ Bp,
               float* __restrict__ C, int M,
               const float* __restrict__ gamma, const float* __restrict__ beta,
               const float* __restrict__ mean,  const float* __restrict__ var)
{
    extern __shared__ char sm[];
    const int tid  = threadIdx.x;
    const int wid  = tid >> 5;
    const int lane = tid & 31;
    const int g    = lane >> 2;
    const int tig  = lane & 3;

    const int n0 = blockIdx.x * 128;
    const int m0 = blockIdx.y * 128;
    const int z  = blockIdx.z;

    const int wm = (wid & 3) * 32;
    const int wn = (wid >> 2) * 64;

    constexpr int ROWB = NCH * 128;
    const char* Ab = (const char*)Ap;
    const char* Bb = (const char*)Bp + (size_t)z * HW * ROWB;
    float*      Cb = C + (size_t)z * M * HW;

    uint32_t smb;
    asm("{ .reg .u64 t; cvta.to.shared.u64 t, %1; cvt.u32.u64 %0, t; }" : "=r"(smb) : "l"(sm));

    const int frow = tid >> 3;
    const int j16  = (tid & 7) * 16;
    const char* gA = Ab + (size_t)(m0 + frow) * ROWB + j16;
    const char* gB = Bb + (size_t)(n0 + frow) * ROWB + j16;
    const uint32_t sA0 = smb + (uint32_t)(frow * SROW + j16);
    const uint32_t sB0 = sA0 + (uint32_t)ATILE;

    float acc[2][8][4];
    #pragma unroll
    for (int mt = 0; mt < 2; mt++)
        #pragma unroll
        for (int nt = 0; nt < 8; nt++)
            #pragma unroll
            for (int j = 0; j < 4; j++) acc[mt][nt][j] = 0.f;

    #pragma unroll
    for (int it = 0; it < 4; it++) {
        CP_ASYNC16(sA0 + (uint32_t)(it * 32 * SROW), gA + (size_t)it * 32 * ROWB);
        CP_ASYNC16(sB0 + (uint32_t)(it * 32 * SROW), gB + (size_t)it * 32 * ROWB);
    }
    CP_COMMIT();
    gA += 128;
    gB += 128;

    for (int c = 0; c < NCH; c++) {
        CP_WAIT_ALL();
        __syncthreads();
        if (c + 1 < NCH) {
            const uint32_t so = ((c + 1) & 1) ? (uint32_t)STGB : 0u;
            #pragma unroll
            for (int it = 0; it < 4; it++) {
                CP_ASYNC16(sA0 + so + (uint32_t)(it * 32 * SROW),
                           gA + (size_t)it * 32 * ROWB);
                CP_ASYNC16(sB0 + so + (uint32_t)(it * 32 * SROW),
                           gB + (size_t)it * 32 * ROWB);
            }
            CP_COMMIT();
            gA += 128;
            gB += 128;
        }
        const char* As_ = sm + (c & 1) * STGB;
        const char* Bs_ = As_ + ATILE;

        #pragma unroll
        for (int ks = 0; ks < 2; ks++) {
            const int col = ks * 64 + tig * 16;
            float4 r1 = *(const float4*)(As_ + (wm + g     ) * SROW + col);
            float4 r2 = *(const float4*)(As_ + (wm + 8  + g) * SROW + col);
            float4 r3 = *(const float4*)(As_ + (wm + 16 + g) * SROW + col);
            float4 r4 = *(const float4*)(As_ + (wm + 24 + g) * SROW + col);
            uint32_t ahi0[4] = { __float_as_uint(r1.x), __float_as_uint(r2.x),
                                 __float_as_uint(r1.z), __float_as_uint(r2.z) };
            uint32_t alo0[4] = { __float_as_uint(r1.y), __float_as_uint(r2.y),
                                 __float_as_uint(r1.w), __float_as_uint(r2.w) };
            uint32_t ahi1[4] = { __float_as_uint(r3.x), __float_as_uint(r4.x),
                                 __float_as_uint(r3.z), __float_as_uint(r4.z) };
            uint32_t alo1[4] = { __float_as_uint(r3.y), __float_as_uint(r4.y),
                                 __float_as_uint(r3.w), __float_as_uint(r4.w) };

            #pragma unroll
            for (int np = 0; np < 4; np++) {
                const int na = np * 2;
                const int nb = na + 1;
                float4 rb0 = *(const float4*)(Bs_ + (wn + na * 8 + g) * SROW + col);
                float4 rb1 = *(const float4*)(Bs_ + (wn + nb * 8 + g) * SROW + col);
                uint32_t b0h[2] = { __float_as_uint(rb0.x), __float_as_uint(rb0.z) };
                uint32_t b1h[2] = { __float_as_uint(rb1.x), __float_as_uint(rb1.z) };
                mma_f16(acc[0][na], alo0, b0h);
                mma_f16(acc[1][na], alo1, b0h);
                mma_f16(acc[0][nb], alo0, b1h);
                mma_f16(acc[1][nb], alo1, b1h);
                if (TERMS == 3) {
                    uint32_t b0l[2] = { __float_as_uint(rb0.y), __float_as_uint(rb0.w) };
                    uint32_t b1l[2] = { __float_as_uint(rb1.y), __float_as_uint(rb1.w) };
                    mma_f16(acc[0][na], ahi0, b0l);
                    mma_f16(acc[1][na], ahi1, b0l);
                    mma_f16(acc[0][nb], ahi0, b1l);
                    mma_f16(acc[1][nb], ahi1, b1l);
                }
                mma_f16(acc[0][na], ahi0, b0h);
                mma_f16(acc[1][na], ahi1, b0h);
                mma_f16(acc[0][nb], ahi0, b1h);
                mma_f16(acc[1][nb], ahi1, b1h);
            }
        }
    }

    #pragma unroll
    for (int mt = 0; mt < 2; mt++) {
        const int mA = m0 + wm + mt * 16 + g;
        const int mB = mA + 8;
        float sAa = INV_WSCALE, hA = 0.f, sBb = INV_WSCALE, hB = 0.f;
        if (BN) {
            const float invA = gamma[mA] * rsqrtf(var[mA] + 1e-5f);
            const float invB = gamma[mB] * rsqrtf(var[mB] + 1e-5f);
            sAa = invA * INV_WSCALE;
            hA  = beta[mA] - mean[mA] * invA;
            sBb = invB * INV_WSCALE;
            hB  = beta[mB] - mean[mB] * invB;
        }
        float* rowA = Cb + (size_t)mA * HW + n0 + wn + 2 * tig;
        float* rowB = Cb + (size_t)mB * HW + n0 + wn + 2 * tig;
        #pragma unroll
        for (int nt = 0; nt < 8; nt++) {
            *(float2*)(rowA + nt * 8) =
                make_float2(acc[mt][nt][0] * sAa + hA, acc[mt][nt][1] * sAa + hA);
            *(float2*)(rowB + nt * 8) =
                make_float2(acc[mt][nt][2] * sBb + hB, acc[mt][nt][3] * sBb + hB);
        }
    }
}

// ---------------------------------------------------------------------------
// Transpose x: [b][k=256][n] -> paired fp16 xt [b][n][16 chunks][32 halves]
// ---------------------------------------------------------------------------
__global__ __launch_bounds__(256)
void transpose_kernel(const float* __restrict__ in, __half* __restrict__ outp)
{
    __shared__ float t[32][33];
    const int b  = blockIdx.z;
    const int n0 = blockIdx.x * 32;
    const int k0 = blockIdx.y * 32;
    const int tx = threadIdx.x & 31;
    const int ty = threadIdx.x >> 5;

    const float* ib = in + (size_t)b * CIN * HW;
    __half* ob = outp + (size_t)b * HW * (2 * CIN);

    #pragma unroll
    for (int i = 0; i < 4; i++) {
        const int k = k0 + ty + i * 8;
        t[ty + i * 8][tx] = ib[(size_t)k * HW + n0 + tx];
    }
    __syncthreads();
    #pragma unroll
    for (int i = 0; i < 4; i++) {
        const int n = n0 + ty + i * 8;
        const int k = k0 + tx;
        const float v = t[tx][ty + i * 8];
        const __half h = __float2half_rn(v);
        const __half l = __float2half_rn(v - __half2float(h));
        __half* dst = ob + (size_t)n * (2 * CIN) + (k >> 4) * 32;
        const int off = slot_hi(k & 15);
        dst[off]     = h;
        dst[off + 2] = l;
    }
}

// ---------------------------------------------------------------------------
// Fused depthwise 3x3 + grouped 1x1 (fp32)
// ---------------------------------------------------------------------------
__global__ __launch_bounds__(256)
void dwpw_kernel(const float* __restrict__ qkv,
                 const float* __restrict__ wdw,
                 const float* __restrict__ wpw,
                 float* __restrict__ agg)
{
    const int strip = blockIdx.x;
    const int gg    = blockIdx.y;
    const int b     = blockIdx.z;
    const int r0    = strip * 16;

    __shared__ float s_in[8][18][68];
    __shared__ float s_wdw[8][9];
    __shared__ float s_wpw[8][8];

    const int tid = threadIdx.x;
    const float* base = qkv + ((size_t)b * OC_QKV + gg * 8) * HW;

    for (int idx = tid; idx < 8 * 18 * 16; idx += 256) {
        const int seg = idx & 15;
        const int row = idx >> 4;
        const int rr  = row % 18;
        const int ch  = row / 18;
        const int y   = r0 + rr - 1;
        float4 v = make_float4(0.f, 0.f, 0.f, 0.f);
        if (y >= 0 && y < HH)
            v = *(const float4*)(base + (size_t)ch * HW + y * WW + seg * 4);
        float* d = &s_in[ch][rr][1 + seg * 4];
        d[0] = v.x; d[1] = v.y; d[2] = v.z; d[3] = v.w;
        if (seg == 0)  s_in[ch][rr][0]  = 0.f;
        if (seg == 15) s_in[ch][rr][65] = 0.f;
    }
    if (tid < 72)
        s_wdw[tid / 9][tid % 9] = wdw[(size_t)(gg * 8 + tid / 9) * 9 + tid % 9];
    if (tid >= 128 && tid < 192) {
        int t = tid - 128;
        s_wpw[t >> 3][t & 7] = wpw[(size_t)(gg * 8 + (t >> 3)) * 8 + (t & 7)];
    }
    __syncthreads();

    float* obase = agg + ((size_t)b * OC_QKV + gg * 8) * HW + r0 * WW;
    for (int p = tid; p < 16 * WW; p += 256) {
        const int py = p >> 6;
        const int px = p & 63;
        float dwv[8];
        #pragma unroll
        for (int ic = 0; ic < 8; ic++) {
            float s = 0.f;
            #pragma unroll
            for (int ky = 0; ky < 3; ky++)
                #pragma unroll
                for (int kx = 0; kx < 3; kx++)
                    s += s_in[ic][py + ky][px + kx] * s_wdw[ic][ky * 3 + kx];
            dwv[ic] = s;
        }
        #pragma unroll
        for (int oc = 0; oc < 8; oc++) {
            float s = 0.f;
            #pragma unroll
            for (int ic = 0; ic < 8; ic++) s += s_wpw[oc][ic] * dwv[ic];
            obase[(size_t)oc * HW + p] = s;
        }
    }
}

// ---------------------------------------------------------------------------
// kv partial reduction over 4 n-segments
// ---------------------------------------------------------------------------
__global__ __launch_bounds__(256)
void kv_kernel(const float* __restrict__ qkv, const float* __restrict__ agg,
               float* __restrict__ kvout)
{
    const int h   = blockIdx.x;
    const int b   = blockIdx.y;
    const int seg = blockIdx.z;
    const float* src = (h < 32) ? qkv : agg;
    const int ch0 = (h & 31) * 24;
    const float* base = src + ((size_t)b * OC_QKV + ch0) * HW;

    float acc[8][9];
    #pragma unroll
    for (int d = 0; d < 8; d++)
        #pragma unroll
        for (int e = 0; e < 9; e++) acc[d][e] = 0.f;

    const int nend = (seg + 1) * 1024;
    for (int n = seg * 1024 + threadIdx.x; n < nend; n += 256) {
        float kk[8], vv[8];
        #pragma unroll
        for (int d = 0; d < 8; d++)
            kk[d] = fmaxf(base[(size_t)(8 + d) * HW + n], 0.f);
        #pragma unroll
        for (int e = 0; e < 8; e++)
            vv[e] = base[(size_t)(16 + e) * HW + n];
        #pragma unroll
        for (int d = 0; d < 8; d++) {
            #pragma unroll
            for (int e = 0; e < 8; e++) acc[d][e] += kk[d] * vv[e];
            acc[d][8] += kk[d];
        }
    }

    __shared__ float sred[8][72];
    const int lane = threadIdx.x & 31;
    const int warp = threadIdx.x >> 5;
    #pragma unroll
    for (int d = 0; d < 8; d++)
        #pragma unroll
        for (int e = 0; e < 9; e++) {
            float v = acc[d][e];
            #pragma unroll
            for (int o = 16; o > 0; o >>= 1)
                v += __shfl_down_sync(0xffffffffu, v, o);
            if (lane == 0) sred[warp][d * 9 + e] = v;
        }
    __syncthreads();
    if (threadIdx.x < 72) {
        float s = 0.f;
        #pragma unroll
        for (int w = 0; w < 8; w++) s += sred[w][threadIdx.x];
        kvout[(((size_t)b * HEADS + h) * 4 + seg) * 72 + threadIdx.x] = s;
    }
}

// ---------------------------------------------------------------------------
// attention apply, head-pair per block, smem-staged coalesced stores.
// Block (hp, b) handles heads 2hp, 2hp+1 -> full 64B column per n.
// att lo slots written as 0 (2-term GEMM2 never reads them).
// Staging pitch 80B; drain in 8B (uint2) units: warp covers 4 x 64B
// contiguous gmem segments -> full sectors. All accesses 8B-aligned.
// ---------------------------------------------------------------------------
__global__ __launch_bounds__(256)
void apply_kernel(const float* __restrict__ qkv, const float* __restrict__ agg,
                  const float* __restrict__ kvin, __half* __restrict__ attp)
{
    const int hp = blockIdx.x;              // 0..31
    const int b  = blockIdx.y;
    const int h0 = hp * 2;
    const float* src = (h0 < 32) ? qkv : agg;
    const int ch0 = (h0 & 31) * 24;         // head h0 group; h1 = +24
    const float* qb0 = src + ((size_t)b * OC_QKV + ch0) * HW;
    const float* qb1 = qb0 + (size_t)24 * HW;

    __shared__ float s_kv[2][72];
    __shared__ uint2 s_out[256][10];        // 8 slots + 16B pad (80B pitch)

    const int tid = threadIdx.x;
    if (tid < 144) {
        const int hh = tid / 72;
        const int ii = tid - hh * 72;
        const float* kp = kvin + ((size_t)b * HEADS + h0 + hh) * 4 * 72 + ii;
        s_kv[hh][ii] = kp[0] + kp[72] + kp[144] + kp[216];
    }
    __syncthreads();

    char* obase = (char*)attp + (size_t)b * HW * 2048 + hp * 64;

    for (int n0 = 0; n0 < HW; n0 += 256) {
        const int n = n0 + tid;
        float q0[8], q1[8];
        #pragma unroll
        for (int d = 0; d < 8; d++) {
            q0[d] = fmaxf(qb0[(size_t)d * HW + n], 0.f);
            q1[d] = fmaxf(qb1[(size_t)d * HW + n], 0.f);
        }
        float num0[9], num1[9];
        #pragma unroll
        for (int e = 0; e < 9; e++) {
            float s0 = 0.f, s1 = 0.f;
            #pragma unroll
            for (int d = 0; d < 8; d++) {
                s0 += q0[d] * s_kv[0][d * 9 + e];
                s1 += q1[d] * s_kv[1][d * 9 + e];
            }
            num0[e] = s0;
            num1[e] = s1;
        }
        const float r0 = 1.0f / (num0[8] + 1e-15f);
        const float r1 = 1.0f / (num1[8] + 1e-15f);
        // stage 64B: slots 2j -> head0 pair j, 2j+1 -> head1 pair j; lo = 0
        #pragma unroll
        for (int j = 0; j < 4; j++) {
            __half2 p0 = __halves2half2(__float2half_rn(num0[2 * j] * r0),
                                        __float2half_rn(num0[2 * j + 1] * r0));
            __half2 p1 = __halves2half2(__float2half_rn(num1[2 * j] * r1),
                                        __float2half_rn(num1[2 * j + 1] * r1));
            uint2 w0, w1;
            w0.x = *reinterpret_cast<unsigned*>(&p0); w0.y = 0u;
            w1.x = *reinterpret_cast<unsigned*>(&p1); w1.y = 0u;
            s_out[tid][2 * j]     = w0;
            s_out[tid][2 * j + 1] = w1;
        }
        __syncthreads();
        // coalesced drain: 2048 x 8B, 8 per thread
        #pragma unroll
        for (int rix = 0; rix < 8; rix++) {
            const int i    = tid + rix * 256;
            const int nl   = i >> 3;
            const int slot = i & 7;
            uint2 v = s_out[nl][slot];
            *(uint2*)(obase + (size_t)(n0 + nl) * 2048 + slot * 8) = v;
        }
        __syncthreads();
    }
}

// ---------------------------------------------------------------------------
// Launch
// ---------------------------------------------------------------------------
extern "C" void kernel_launch(void* const* d_in, const int* in_sizes, int n_in,
                              void* d_out, int out_size)
{
    const float* x      = (const float*)d_in[0];
    const float* w_qkv  = (const float*)d_in[1];
    const float* w_dw   = (const float*)d_in[2];
    const float* w_pw   = (const float*)d_in[3];
    const float* w_proj = (const float*)d_in[4];
    const float* gamma  = (const float*)d_in[5];
    const float* beta   = (const float*)d_in[6];
    const float* mean   = (const float*)d_in[7];
    const float* var    = (const float*)d_in[8];
    float* out = (float*)d_out;

    float *qkv_p, *agg_p, *kv_p;
    __half *attp_p, *xtp_p, *wqp_p, *wpp_p;
    cudaGetSymbolAddress((void**)&qkv_p,  g_qkv);
    cudaGetSymbolAddress((void**)&agg_p,  g_agg);
    cudaGetSymbolAddress((void**)&kv_p,   g_kv);
    cudaGetSymbolAddress((void**)&attp_p, g_attp);
    cudaGetSymbolAddress((void**)&xtp_p,  g_xtp);
    cudaGetSymbolAddress((void**)&wqp_p,  g_wqp);
    cudaGetSymbolAddress((void**)&wpp_p,  g_wpp);

    cudaFuncSetAttribute(gemm_fp16<8, 3, false>,
                         cudaFuncAttributeMaxDynamicSharedMemorySize, GEMM_SMEM);
    cudaFuncSetAttribute(gemm_fp16<16, 2, true>,
                         cudaFuncAttributeMaxDynamicSharedMemorySize, GEMM_SMEM);

    split_kernel<<<(OC_QKV * CIN + 255) / 256, 256>>>(w_qkv, wqp_p, OC_QKV, CIN, WSCALE);
    split_kernel<<<(OC_OUT * K_PROJ + 255) / 256, 256>>>(w_proj, wpp_p, OC_OUT, K_PROJ, WSCALE);
    {
        dim3 grid(HW / 32, CIN / 32, BATCH);
        transpose_kernel<<<grid, 256>>>(x, xtp_p);
    }
    // 1) qkv = W_qkv * x : fp16 3-term, K=256 -> NCH=8
    {
        dim3 grid(HW / 128, OC_QKV / 128, BATCH);
        gemm_fp16<8, 3, false><<<grid, 256, GEMM_SMEM>>>(wqp_p, xtp_p, qkv_p, OC_QKV,
                                                         nullptr, nullptr, nullptr, nullptr);
    }
    // 2) depthwise + grouped pointwise
    {
        dim3 grid(4, 96, BATCH);
        dwpw_kernel<<<grid, 256>>>(qkv_p, w_dw, w_pw, agg_p);
    }
    // 3) kv partial reduction
    {
        dim3 grid(HEADS, BATCH, 4);
        kv_kernel<<<grid, 256>>>(qkv_p, agg_p, kv_p);
    }
    // 4) attention apply (head-pair blocks, staged coalesced stores)
    {
        dim3 grid(HEADS / 2, BATCH);
        apply_kernel<<<grid, 256>>>(qkv_p, agg_p, kv_p, attp_p);
    }
    // 5) y = W_proj * att + BN : fp16 2-term (terminal), K=512 -> NCH=16
    {
        dim3 grid(HW / 128, OC_OUT / 128, BATCH);
        gemm_fp16<16, 2, true><<<grid, 256, GEMM_SMEM>>>(wpp_p, attp_p, out, OC_OUT,
                                                         gamma, beta, mean, var);
    }
}

// round 17
// speedup vs baseline: 1.3785x; 1.0090x over previous
#include <cuda_runtime.h>
#include <cuda_fp16.h>
#include <cstdint>
#include <cstddef>

// Problem constants
#define BATCH   16
#define CIN     256
#define HH      64
#define WW      64
#define HW      4096
#define OC_QKV  768
#define HEADS   64
#define ATT_CH  512
#define OC_OUT  256
#define K_PROJ  512

#define WSCALE    2048.0f
#define INV_WSCALE (1.0f / 2048.0f)

// ---------------------------------------------------------------------------
// Paired fp16 hi/lo layout (A operands + GEMM1 B), 16-k chunks, 32 halves/row:
//   slot s(p) = ((p&3)<<1)|(p>>2), pair p=kk>>1; slot 8B = [h_e,h_o,l_e,l_o].
// Hi-only layout (GEMM2 B / att), 32-k chunks, 32 halves (64B)/row:
//   byte off of k: (kk>>4)*32 + ((kk&15)>>1 &3)*8 + (((kk&15)>>1)>>2)*4 + (kk&1)*2
// ---------------------------------------------------------------------------
__device__ float  g_qkv [(size_t)BATCH * OC_QKV * HW];
__device__ float  g_agg [(size_t)BATCH * OC_QKV * HW];
__device__ float  g_kv  [(size_t)BATCH * HEADS * 4 * 72];
__device__ __half g_attp[(size_t)BATCH * HW * ATT_CH];      // hi-only fp16
__device__ __half g_xtp [(size_t)BATCH * HW * 2 * CIN];     // paired fp16
__device__ __half g_wqp [(size_t)OC_QKV * 2 * CIN];
__device__ __half g_wpp [(size_t)OC_OUT * 2 * K_PROJ];

// ---------------------------------------------------------------------------
// Helpers
// ---------------------------------------------------------------------------
__device__ __forceinline__ int slot_hi(int kk) {
    const int p = kk >> 1;
    const int s = ((p & 3) << 1) | (p >> 2);
    return s * 4 + (kk & 1);
}
__device__ __forceinline__ void mma_f16(float* d, const uint32_t* a, const uint32_t* b) {
    asm volatile(
        "mma.sync.aligned.m16n8k16.row.col.f32.f16.f16.f32 "
        "{%0,%1,%2,%3}, {%4,%5,%6,%7}, {%8,%9}, {%0,%1,%2,%3};"
        : "+f"(d[0]), "+f"(d[1]), "+f"(d[2]), "+f"(d[3])
        : "r"(a[0]), "r"(a[1]), "r"(a[2]), "r"(a[3]), "r"(b[0]), "r"(b[1]));
}
#define CP_ASYNC16(sa, gp) \
    asm volatile("cp.async.ca.shared.global [%0], [%1], 16;" :: "r"(sa), "l"(gp))
#define CP_COMMIT() asm volatile("cp.async.commit_group;")
#define CP_WAIT_ALL() asm volatile("cp.async.wait_group 0;")

// ---------------------------------------------------------------------------
// Splitter: fp32 [M,K] row-major -> fp16 hi/lo paired [m][K/16][32 halves]
// ---------------------------------------------------------------------------
__global__ __launch_bounds__(256)
void split_kernel(const float* __restrict__ in, __half* __restrict__ out,
                  int M, int K, float scale)
{
    const int i = blockIdx.x * 256 + threadIdx.x;
    if (i >= M * K) return;
    const int m = i / K;
    const int k = i - m * K;
    const float v = in[i] * scale;
    const __half h = __float2half_rn(v);
    const __half l = __float2half_rn(v - __half2float(h));
    __half* dst = out + ((size_t)m * (K >> 4) + (k >> 4)) * 32;
    const int off = slot_hi(k & 15);
    dst[off]     = h;
    dst[off + 2] = l;
}

// ---------------------------------------------------------------------------
// GEMM1: fp16 3-term (AlBh + AhBl + AhBh), paired A + paired B.
// K-chunk 32 (2 x k16 per sync), SROW=192 (conflict-free), 2-stage, 2 CTAs/SM.
// Block 128x128, 8 warps @ 32(M) x 64(N).
// ---------------------------------------------------------------------------
#define SROW 192
#define ATILE (128 * SROW)                 // 24576 B
#define STGB  (2 * ATILE)
#define GEMM_SMEM (2 * STGB)               // 98304 B

template<int NCH>
__global__ __launch_bounds__(256, 2)
void gemm_fp16(const __half* __restrict__ Ap, const __half* __restrict__ Bp,
               float* __restrict__ C, int M)
{
    extern __shared__ char sm[];
    const int tid  = threadIdx.x;
    const int wid  = tid >> 5;
    const int lane = tid & 31;
    const int g    = lane >> 2;
    const int tig  = lane & 3;

    const int n0 = blockIdx.x * 128;
    const int m0 = blockIdx.y * 128;
    const int z  = blockIdx.z;

    const int wm = (wid & 3) * 32;
    const int wn = (wid >> 2) * 64;

    constexpr int ROWB = NCH * 128;
    const char* Ab = (const char*)Ap;
    const char* Bb = (const char*)Bp + (size_t)z * HW * ROWB;
    float*      Cb = C + (size_t)z * M * HW;

    uint32_t smb;
    asm("{ .reg .u64 t; cvta.to.shared.u64 t, %1; cvt.u32.u64 %0, t; }" : "=r"(smb) : "l"(sm));

    const int frow = tid >> 3;
    const int j16  = (tid & 7) * 16;
    const char* gA = Ab + (size_t)(m0 + frow) * ROWB + j16;
    const char* gB = Bb + (size_t)(n0 + frow) * ROWB + j16;
    const uint32_t sA0 = smb + (uint32_t)(frow * SROW + j16);
    const uint32_t sB0 = sA0 + (uint32_t)ATILE;

    float acc[2][8][4];
    #pragma unroll
    for (int mt = 0; mt < 2; mt++)
        #pragma unroll
        for (int nt = 0; nt < 8; nt++)
            #pragma unroll
            for (int j = 0; j < 4; j++) acc[mt][nt][j] = 0.f;

    #pragma unroll
    for (int it = 0; it < 4; it++) {
        CP_ASYNC16(sA0 + (uint32_t)(it * 32 * SROW), gA + (size_t)it * 32 * ROWB);
        CP_ASYNC16(sB0 + (uint32_t)(it * 32 * SROW), gB + (size_t)it * 32 * ROWB);
    }
    CP_COMMIT();
    gA += 128;
    gB += 128;

    for (int c = 0; c < NCH; c++) {
        CP_WAIT_ALL();
        __syncthreads();
        if (c + 1 < NCH) {
            const uint32_t so = ((c + 1) & 1) ? (uint32_t)STGB : 0u;
            #pragma unroll
            for (int it = 0; it < 4; it++) {
                CP_ASYNC16(sA0 + so + (uint32_t)(it * 32 * SROW),
                           gA + (size_t)it * 32 * ROWB);
                CP_ASYNC16(sB0 + so + (uint32_t)(it * 32 * SROW),
                           gB + (size_t)it * 32 * ROWB);
            }
            CP_COMMIT();
            gA += 128;
            gB += 128;
        }
        const char* As_ = sm + (c & 1) * STGB;
        const char* Bs_ = As_ + ATILE;

        #pragma unroll
        for (int ks = 0; ks < 2; ks++) {
            const int col = ks * 64 + tig * 16;
            float4 r1 = *(const float4*)(As_ + (wm + g     ) * SROW + col);
            float4 r2 = *(const float4*)(As_ + (wm + 8  + g) * SROW + col);
            float4 r3 = *(const float4*)(As_ + (wm + 16 + g) * SROW + col);
            float4 r4 = *(const float4*)(As_ + (wm + 24 + g) * SROW + col);
            uint32_t ahi0[4] = { __float_as_uint(r1.x), __float_as_uint(r2.x),
                                 __float_as_uint(r1.z), __float_as_uint(r2.z) };
            uint32_t alo0[4] = { __float_as_uint(r1.y), __float_as_uint(r2.y),
                                 __float_as_uint(r1.w), __float_as_uint(r2.w) };
            uint32_t ahi1[4] = { __float_as_uint(r3.x), __float_as_uint(r4.x),
                                 __float_as_uint(r3.z), __float_as_uint(r4.z) };
            uint32_t alo1[4] = { __float_as_uint(r3.y), __float_as_uint(r4.y),
                                 __float_as_uint(r3.w), __float_as_uint(r4.w) };

            #pragma unroll
            for (int np = 0; np < 4; np++) {
                const int na = np * 2;
                const int nb = na + 1;
                float4 rb0 = *(const float4*)(Bs_ + (wn + na * 8 + g) * SROW + col);
                float4 rb1 = *(const float4*)(Bs_ + (wn + nb * 8 + g) * SROW + col);
                uint32_t b0h[2] = { __float_as_uint(rb0.x), __float_as_uint(rb0.z) };
                uint32_t b0l[2] = { __float_as_uint(rb0.y), __float_as_uint(rb0.w) };
                uint32_t b1h[2] = { __float_as_uint(rb1.x), __float_as_uint(rb1.z) };
                uint32_t b1l[2] = { __float_as_uint(rb1.y), __float_as_uint(rb1.w) };
                mma_f16(acc[0][na], alo0, b0h);
                mma_f16(acc[1][na], alo1, b0h);
                mma_f16(acc[0][nb], alo0, b1h);
                mma_f16(acc[1][nb], alo1, b1h);
                mma_f16(acc[0][na], ahi0, b0l);
                mma_f16(acc[1][na], ahi1, b0l);
                mma_f16(acc[0][nb], ahi0, b1l);
                mma_f16(acc[1][nb], ahi1, b1l);
                mma_f16(acc[0][na], ahi0, b0h);
                mma_f16(acc[1][na], ahi1, b0h);
                mma_f16(acc[0][nb], ahi0, b1h);
                mma_f16(acc[1][nb], ahi1, b1h);
            }
        }
    }

    #pragma unroll
    for (int mt = 0; mt < 2; mt++) {
        const int mA = m0 + wm + mt * 16 + g;
        const int mB = mA + 8;
        float* rowA = Cb + (size_t)mA * HW + n0 + wn + 2 * tig;
        float* rowB = Cb + (size_t)mB * HW + n0 + wn + 2 * tig;
        #pragma unroll
        for (int nt = 0; nt < 8; nt++) {
            *(float2*)(rowA + nt * 8) = make_float2(acc[mt][nt][0] * INV_WSCALE,
                                                    acc[mt][nt][1] * INV_WSCALE);
            *(float2*)(rowB + nt * 8) = make_float2(acc[mt][nt][2] * INV_WSCALE,
                                                    acc[mt][nt][3] * INV_WSCALE);
        }
    }
}

// ---------------------------------------------------------------------------
// GEMM2: fp16 2-term (AlBh + AhBh), paired A + HI-ONLY B (64B/row/chunk).
// SROWB=96 (64 data + 32 pad): frag LDS.64 16-lane phase conflict-free.
// NCH=16 chunks of 32k. Fused BN epilogue. 2-stage, 2 CTAs/SM.
// ---------------------------------------------------------------------------
#define SROWB 96
#define BTILE (128 * SROWB)                // 12288 B
#define STGB2 (ATILE + BTILE)              // 36864 B
#define GEMM2_SMEM (2 * STGB2)             // 73728 B

__global__ __launch_bounds__(256, 2)
void gemm2_hi(const __half* __restrict__ Ap, const __half* __restrict__ Bp,
              float* __restrict__ C,
              const float* __restrict__ gamma, const float* __restrict__ beta,
              const float* __restrict__ mean,  const float* __restrict__ var)
{
    extern __shared__ char sm[];
    const int tid  = threadIdx.x;
    const int wid  = tid >> 5;
    const int lane = tid & 31;
    const int g    = lane >> 2;
    const int tig  = lane & 3;

    const int n0 = blockIdx.x * 128;
    const int m0 = blockIdx.y * 128;
    const int z  = blockIdx.z;

    const int wm = (wid & 3) * 32;
    const int wn = (wid >> 2) * 64;

    constexpr int NCH   = 16;
    constexpr int ROWBA = NCH * 128;        // 2048 B
    constexpr int ROWBB = NCH * 64;         // 1024 B
    const char* Ab = (const char*)Ap;
    const char* Bb = (const char*)Bp + (size_t)z * HW * ROWBB;
    float*      Cb = C + (size_t)z * OC_OUT * HW;

    uint32_t smb;
    asm("{ .reg .u64 t; cvta.to.shared.u64 t, %1; cvt.u32.u64 %0, t; }" : "=r"(smb) : "l"(sm));

    // A fill (as GEMM1)
    const int frowA = tid >> 3;
    const int j16   = (tid & 7) * 16;
    const char* gA = Ab + (size_t)(m0 + frowA) * ROWBA + j16;
    const uint32_t sA0 = smb + (uint32_t)(frowA * SROW + j16);
    // B fill: frowB = tid&127, uoB = (tid>>7)*32; 2 x 16B per chunk
    const int frowB = tid & 127;
    const int uoB   = (tid >> 7) * 32;
    const char* gB = Bb + (size_t)(n0 + frowB) * ROWBB + uoB;
    const uint32_t sB0 = smb + (uint32_t)ATILE + (uint32_t)(frowB * SROWB + uoB);

    float acc[2][8][4];
    #pragma unroll
    for (int mt = 0; mt < 2; mt++)
        #pragma unroll
        for (int nt = 0; nt < 8; nt++)
            #pragma unroll
            for (int j = 0; j < 4; j++) acc[mt][nt][j] = 0.f;

    #pragma unroll
    for (int it = 0; it < 4; it++)
        CP_ASYNC16(sA0 + (uint32_t)(it * 32 * SROW), gA + (size_t)it * 32 * ROWBA);
    CP_ASYNC16(sB0,      gB);
    CP_ASYNC16(sB0 + 16, gB + 16);
    CP_COMMIT();
    gA += 128;
    gB += 64;

    for (int c = 0; c < NCH; c++) {
        CP_WAIT_ALL();
        __syncthreads();
        if (c + 1 < NCH) {
            const uint32_t so = ((c + 1) & 1) ? (uint32_t)STGB2 : 0u;
            #pragma unroll
            for (int it = 0; it < 4; it++)
                CP_ASYNC16(sA0 + so + (uint32_t)(it * 32 * SROW),
                           gA + (size_t)it * 32 * ROWBA);
            CP_ASYNC16(sB0 + so,      gB);
            CP_ASYNC16(sB0 + so + 16, gB + 16);
            CP_COMMIT();
            gA += 128;
            gB += 64;
        }
        const char* As_ = sm + (c & 1) * STGB2;
        const char* Bs_ = As_ + ATILE;

        #pragma unroll
        for (int ks = 0; ks < 2; ks++) {
            const int colA = ks * 64 + tig * 16;
            const int colB = ks * 32 + tig * 8;
            float4 r1 = *(const float4*)(As_ + (wm + g     ) * SROW + colA);
            float4 r2 = *(const float4*)(As_ + (wm + 8  + g) * SROW + colA);
            float4 r3 = *(const float4*)(As_ + (wm + 16 + g) * SROW + colA);
            float4 r4 = *(const float4*)(As_ + (wm + 24 + g) * SROW + colA);
            uint32_t ahi0[4] = { __float_as_uint(r1.x), __float_as_uint(r2.x),
                                 __float_as_uint(r1.z), __float_as_uint(r2.z) };
            uint32_t alo0[4] = { __float_as_uint(r1.y), __float_as_uint(r2.y),
                                 __float_as_uint(r1.w), __float_as_uint(r2.w) };
            uint32_t ahi1[4] = { __float_as_uint(r3.x), __float_as_uint(r4.x),
                                 __float_as_uint(r3.z), __float_as_uint(r4.z) };
            uint32_t alo1[4] = { __float_as_uint(r3.y), __float_as_uint(r4.y),
                                 __float_as_uint(r3.w), __float_as_uint(r4.w) };

            #pragma unroll
            for (int np = 0; np < 4; np++) {
                const int na = np * 2;
                const int nb = na + 1;
                float2 rb0 = *(const float2*)(Bs_ + (wn + na * 8 + g) * SROWB + colB);
                float2 rb1 = *(const float2*)(Bs_ + (wn + nb * 8 + g) * SROWB + colB);
                uint32_t b0[2] = { __float_as_uint(rb0.x), __float_as_uint(rb0.y) };
                uint32_t b1[2] = { __float_as_uint(rb1.x), __float_as_uint(rb1.y) };
                mma_f16(acc[0][na], alo0, b0);
                mma_f16(acc[1][na], alo1, b0);
                mma_f16(acc[0][nb], alo0, b1);
                mma_f16(acc[1][nb], alo1, b1);
                mma_f16(acc[0][na], ahi0, b0);
                mma_f16(acc[1][na], ahi1, b0);
                mma_f16(acc[0][nb], ahi0, b1);
                mma_f16(acc[1][nb], ahi1, b1);
            }
        }
    }

    #pragma unroll
    for (int mt = 0; mt < 2; mt++) {
        const int mA = m0 + wm + mt * 16 + g;
        const int mB = mA + 8;
        const float invA = gamma[mA] * rsqrtf(var[mA] + 1e-5f);
        const float invB = gamma[mB] * rsqrtf(var[mB] + 1e-5f);
        const float sAa = invA * INV_WSCALE;
        const float hA  = beta[mA] - mean[mA] * invA;
        const float sBb = invB * INV_WSCALE;
        const float hB  = beta[mB] - mean[mB] * invB;
        float* rowA = Cb + (size_t)mA * HW + n0 + wn + 2 * tig;
        float* rowB = Cb + (size_t)mB * HW + n0 + wn + 2 * tig;
        #pragma unroll
        for (int nt = 0; nt < 8; nt++) {
            *(float2*)(rowA + nt * 8) =
                make_float2(acc[mt][nt][0] * sAa + hA, acc[mt][nt][1] * sAa + hA);
            *(float2*)(rowB + nt * 8) =
                make_float2(acc[mt][nt][2] * sBb + hB, acc[mt][nt][3] * sBb + hB);
        }
    }
}

// ---------------------------------------------------------------------------
// Transpose x: [b][k=256][n] -> paired fp16 xt [b][n][16 chunks][32 halves]
// ---------------------------------------------------------------------------
__global__ __launch_bounds__(256)
void transpose_kernel(const float* __restrict__ in, __half* __restrict__ outp)
{
    __shared__ float t[32][33];
    const int b  = blockIdx.z;
    const int n0 = blockIdx.x * 32;
    const int k0 = blockIdx.y * 32;
    const int tx = threadIdx.x & 31;
    const int ty = threadIdx.x >> 5;

    const float* ib = in + (size_t)b * CIN * HW;
    __half* ob = outp + (size_t)b * HW * (2 * CIN);

    #pragma unroll
    for (int i = 0; i < 4; i++) {
        const int k = k0 + ty + i * 8;
        t[ty + i * 8][tx] = ib[(size_t)k * HW + n0 + tx];
    }
    __syncthreads();
    #pragma unroll
    for (int i = 0; i < 4; i++) {
        const int n = n0 + ty + i * 8;
        const int k = k0 + tx;
        const float v = t[tx][ty + i * 8];
        const __half h = __float2half_rn(v);
        const __half l = __float2half_rn(v - __half2float(h));
        __half* dst = ob + (size_t)n * (2 * CIN) + (k >> 4) * 32;
        const int off = slot_hi(k & 15);
        dst[off]     = h;
        dst[off + 2] = l;
    }
}

// ---------------------------------------------------------------------------
// Fused depthwise 3x3 + grouped 1x1 (fp32)
// ---------------------------------------------------------------------------
__global__ __launch_bounds__(256)
void dwpw_kernel(const float* __restrict__ qkv,
                 const float* __restrict__ wdw,
                 const float* __restrict__ wpw,
                 float* __restrict__ agg)
{
    const int strip = blockIdx.x;
    const int gg    = blockIdx.y;
    const int b     = blockIdx.z;
    const int r0    = strip * 16;

    __shared__ float s_in[8][18][68];
    __shared__ float s_wdw[8][9];
    __shared__ float s_wpw[8][8];

    const int tid = threadIdx.x;
    const float* base = qkv + ((size_t)b * OC_QKV + gg * 8) * HW;

    for (int idx = tid; idx < 8 * 18 * 16; idx += 256) {
        const int seg = idx & 15;
        const int row = idx >> 4;
        const int rr  = row % 18;
        const int ch  = row / 18;
        const int y   = r0 + rr - 1;
        float4 v = make_float4(0.f, 0.f, 0.f, 0.f);
        if (y >= 0 && y < HH)
            v = *(const float4*)(base + (size_t)ch * HW + y * WW + seg * 4);
        float* d = &s_in[ch][rr][1 + seg * 4];
        d[0] = v.x; d[1] = v.y; d[2] = v.z; d[3] = v.w;
        if (seg == 0)  s_in[ch][rr][0]  = 0.f;
        if (seg == 15) s_in[ch][rr][65] = 0.f;
    }
    if (tid < 72)
        s_wdw[tid / 9][tid % 9] = wdw[(size_t)(gg * 8 + tid / 9) * 9 + tid % 9];
    if (tid >= 128 && tid < 192) {
        int t = tid - 128;
        s_wpw[t >> 3][t & 7] = wpw[(size_t)(gg * 8 + (t >> 3)) * 8 + (t & 7)];
    }
    __syncthreads();

    float* obase = agg + ((size_t)b * OC_QKV + gg * 8) * HW + r0 * WW;
    for (int p = tid; p < 16 * WW; p += 256) {
        const int py = p >> 6;
        const int px = p & 63;
        float dwv[8];
        #pragma unroll
        for (int ic = 0; ic < 8; ic++) {
            float s = 0.f;
            #pragma unroll
            for (int ky = 0; ky < 3; ky++)
                #pragma unroll
                for (int kx = 0; kx < 3; kx++)
                    s += s_in[ic][py + ky][px + kx] * s_wdw[ic][ky * 3 + kx];
            dwv[ic] = s;
        }
        #pragma unroll
        for (int oc = 0; oc < 8; oc++) {
            float s = 0.f;
            #pragma unroll
            for (int ic = 0; ic < 8; ic++) s += s_wpw[oc][ic] * dwv[ic];
            obase[(size_t)oc * HW + p] = s;
        }
    }
}

// ---------------------------------------------------------------------------
// kv partial reduction over 4 n-segments
// ---------------------------------------------------------------------------
__global__ __launch_bounds__(256)
void kv_kernel(const float* __restrict__ qkv, const float* __restrict__ agg,
               float* __restrict__ kvout)
{
    const int h   = blockIdx.x;
    const int b   = blockIdx.y;
    const int seg = blockIdx.z;
    const float* src = (h < 32) ? qkv : agg;
    const int ch0 = (h & 31) * 24;
    const float* base = src + ((size_t)b * OC_QKV + ch0) * HW;

    float acc[8][9];
    #pragma unroll
    for (int d = 0; d < 8; d++)
        #pragma unroll
        for (int e = 0; e < 9; e++) acc[d][e] = 0.f;

    const int nend = (seg + 1) * 1024;
    for (int n = seg * 1024 + threadIdx.x; n < nend; n += 256) {
        float kk[8], vv[8];
        #pragma unroll
        for (int d = 0; d < 8; d++)
            kk[d] = fmaxf(base[(size_t)(8 + d) * HW + n], 0.f);
        #pragma unroll
        for (int e = 0; e < 8; e++)
            vv[e] = base[(size_t)(16 + e) * HW + n];
        #pragma unroll
        for (int d = 0; d < 8; d++) {
            #pragma unroll
            for (int e = 0; e < 8; e++) acc[d][e] += kk[d] * vv[e];
            acc[d][8] += kk[d];
        }
    }

    __shared__ float sred[8][72];
    const int lane = threadIdx.x & 31;
    const int warp = threadIdx.x >> 5;
    #pragma unroll
    for (int d = 0; d < 8; d++)
        #pragma unroll
        for (int e = 0; e < 9; e++) {
            float v = acc[d][e];
            #pragma unroll
            for (int o = 16; o > 0; o >>= 1)
                v += __shfl_down_sync(0xffffffffu, v, o);
            if (lane == 0) sred[warp][d * 9 + e] = v;
        }
    __syncthreads();
    if (threadIdx.x < 72) {
        float s = 0.f;
        #pragma unroll
        for (int w = 0; w < 8; w++) s += sred[w][threadIdx.x];
        kvout[(((size_t)b * HEADS + h) * 4 + seg) * 72 + threadIdx.x] = s;
    }
}

// ---------------------------------------------------------------------------
// attention apply, head-pair per block, hi-only att output.
// Head h value d -> byte (hp*32) + (d>>1)*8 + (h&1)*4 + (d&1)*2 in the
// 1024B hi-only row. Block writes 32B per n = one full sector.
// ---------------------------------------------------------------------------
__global__ __launch_bounds__(256)
void apply_kernel(const float* __restrict__ qkv, const float* __restrict__ agg,
                  const float* __restrict__ kvin, __half* __restrict__ attp)
{
    const int hp = blockIdx.x;              // 0..31
    const int b  = blockIdx.y;
    const int h0 = hp * 2;
    const float* src = (h0 < 32) ? qkv : agg;
    const int ch0 = (h0 & 31) * 24;
    const float* qb0 = src + ((size_t)b * OC_QKV + ch0) * HW;
    const float* qb1 = qb0 + (size_t)24 * HW;

    __shared__ float s_kv[2][72];
    __shared__ uint2 s_out[256][5];         // 4 slots + 8B pad (40B pitch)

    const int tid = threadIdx.x;
    if (tid < 144) {
        const int hh = tid / 72;
        const int ii = tid - hh * 72;
        const float* kp = kvin + ((size_t)b * HEADS + h0 + hh) * 4 * 72 + ii;
        s_kv[hh][ii] = kp[0] + kp[72] + kp[144] + kp[216];
    }
    __syncthreads();

    char* obase = (char*)attp + (size_t)b * HW * 1024 + hp * 32;

    for (int n0 = 0; n0 < HW; n0 += 256) {
        const int n = n0 + tid;
        float q0[8], q1[8];
        #pragma unroll
        for (int d = 0; d < 8; d++) {
            q0[d] = fmaxf(qb0[(size_t)d * HW + n], 0.f);
            q1[d] = fmaxf(qb1[(size_t)d * HW + n], 0.f);
        }
        float num0[9], num1[9];
        #pragma unroll
        for (int e = 0; e < 9; e++) {
            float s0 = 0.f, s1 = 0.f;
            #pragma unroll
            for (int d = 0; d < 8; d++) {
                s0 += q0[d] * s_kv[0][d * 9 + e];
                s1 += q1[d] * s_kv[1][d * 9 + e];
            }
            num0[e] = s0;
            num1[e] = s1;
        }
        const float r0 = 1.0f / (num0[8] + 1e-15f);
        const float r1 = 1.0f / (num1[8] + 1e-15f);
        // slot j (8B) = [h0 d=2j, h0 d=2j+1, h1 d=2j, h1 d=2j+1]
        #pragma unroll
        for (int j = 0; j < 4; j++) {
            __half2 p0 = __halves2half2(__float2half_rn(num0[2 * j] * r0),
                                        __float2half_rn(num0[2 * j + 1] * r0));
            __half2 p1 = __halves2half2(__float2half_rn(num1[2 * j] * r1),
                                        __float2half_rn(num1[2 * j + 1] * r1));
            uint2 w;
            w.x = *reinterpret_cast<unsigned*>(&p0);
            w.y = *reinterpret_cast<unsigned*>(&p1);
            s_out[tid][j] = w;
        }
        __syncthreads();
        // drain: 1024 x 8B, 4 per thread; 32B contiguous per n = full sector
        #pragma unroll
        for (int rix = 0; rix < 4; rix++) {
            const int i    = tid + rix * 256;
            const int nl   = i >> 2;
            const int slot = i & 3;
            uint2 v = s_out[nl][slot];
            *(uint2*)(obase + (size_t)(n0 + nl) * 1024 + slot * 8) = v;
        }
        __syncthreads();
    }
}

// ---------------------------------------------------------------------------
// Launch
// ---------------------------------------------------------------------------
extern "C" void kernel_launch(void* const* d_in, const int* in_sizes, int n_in,
                              void* d_out, int out_size)
{
    const float* x      = (const float*)d_in[0];
    const float* w_qkv  = (const float*)d_in[1];
    const float* w_dw   = (const float*)d_in[2];
    const float* w_pw   = (const float*)d_in[3];
    const float* w_proj = (const float*)d_in[4];
    const float* gamma  = (const float*)d_in[5];
    const float* beta   = (const float*)d_in[6];
    const float* mean   = (const float*)d_in[7];
    const float* var    = (const float*)d_in[8];
    float* out = (float*)d_out;

    float *qkv_p, *agg_p, *kv_p;
    __half *attp_p, *xtp_p, *wqp_p, *wpp_p;
    cudaGetSymbolAddress((void**)&qkv_p,  g_qkv);
    cudaGetSymbolAddress((void**)&agg_p,  g_agg);
    cudaGetSymbolAddress((void**)&kv_p,   g_kv);
    cudaGetSymbolAddress((void**)&attp_p, g_attp);
    cudaGetSymbolAddress((void**)&xtp_p,  g_xtp);
    cudaGetSymbolAddress((void**)&wqp_p,  g_wqp);
    cudaGetSymbolAddress((void**)&wpp_p,  g_wpp);

    cudaFuncSetAttribute(gemm_fp16<8>,
                         cudaFuncAttributeMaxDynamicSharedMemorySize, GEMM_SMEM);
    cudaFuncSetAttribute(gemm2_hi,
                         cudaFuncAttributeMaxDynamicSharedMemorySize, GEMM2_SMEM);

    split_kernel<<<(OC_QKV * CIN + 255) / 256, 256>>>(w_qkv, wqp_p, OC_QKV, CIN, WSCALE);
    split_kernel<<<(OC_OUT * K_PROJ + 255) / 256, 256>>>(w_proj, wpp_p, OC_OUT, K_PROJ, WSCALE);
    {
        dim3 grid(HW / 32, CIN / 32, BATCH);
        transpose_kernel<<<grid, 256>>>(x, xtp_p);
    }
    // 1) qkv = W_qkv * x : fp16 3-term, K=256 -> NCH=8
    {
        dim3 grid(HW / 128, OC_QKV / 128, BATCH);
        gemm_fp16<8><<<grid, 256, GEMM_SMEM>>>(wqp_p, xtp_p, qkv_p, OC_QKV);
    }
    // 2) depthwise + grouped pointwise
    {
        dim3 grid(4, 96, BATCH);
        dwpw_kernel<<<grid, 256>>>(qkv_p, w_dw, w_pw, agg_p);
    }
    // 3) kv partial reduction
    {
        dim3 grid(HEADS, BATCH, 4);
        kv_kernel<<<grid, 256>>>(qkv_p, agg_p, kv_p);
    }
    // 4) attention apply (hi-only att, sector-aligned stores)
    {
        dim3 grid(HEADS / 2, BATCH);
        apply_kernel<<<grid, 256>>>(qkv_p, agg_p, kv_p, attp_p);
    }
    // 5) y = W_proj * att + BN : fp16 2-term, hi-only B
    {
        dim3 grid(HW / 128, OC_OUT / 128, BATCH);
        gemm2_hi<<<grid, 256, GEMM2_SMEM>>>(wpp_p, attp_p, out,
                                            gamma, beta, mean, var);
    }
}